// round 2
// baseline (speedup 1.0000x reference)
#include <cuda_runtime.h>
#include <math.h>

#define S_LEN   2048
#define DM      2048
#define KV_DIM  512
#define NHEADS  32
#define NKVH    8
#define HDIM    64

// ---------------- scratch (allocation-free rule: __device__ globals) ----------------
__device__ float g_Q[S_LEN * DM];     // 16 MB
__device__ float g_K[S_LEN * KV_DIM]; //  4 MB
__device__ float g_V[S_LEN * KV_DIM]; //  4 MB
__device__ float g_A[S_LEN * DM];     // 16 MB (attention output, pre-Wo)

// ---------------- SGEMM: C[M,N] = A[M,K] @ B[N,K]^T ----------------
// BM=BN=128, BK=16, 256 threads, 8x8 per thread.
__global__ __launch_bounds__(256) void sgemm_abt(
    const float* __restrict__ A, const float* __restrict__ B,
    float* __restrict__ C, int M, int N, int K)
{
    __shared__ float As[16][128];
    __shared__ float Bs[16][128];

    const int t  = threadIdx.x;
    const int tx = t & 15;        // 0..15 -> n
    const int ty = t >> 4;        // 0..15 -> m
    const int m0 = blockIdx.y * 128;
    const int n0 = blockIdx.x * 128;

    const int lr = t >> 2;        // 0..63
    const int lc = (t & 3) * 4;   // 0,4,8,12

    float acc[8][8];
#pragma unroll
    for (int i = 0; i < 8; ++i)
#pragma unroll
        for (int j = 0; j < 8; ++j) acc[i][j] = 0.f;

    for (int k0 = 0; k0 < K; k0 += 16) {
#pragma unroll
        for (int p = 0; p < 2; ++p) {
            int row = lr + p * 64;
            float4 va = *(const float4*)&A[(size_t)(m0 + row) * K + k0 + lc];
            As[lc + 0][row] = va.x; As[lc + 1][row] = va.y;
            As[lc + 2][row] = va.z; As[lc + 3][row] = va.w;
            float4 vb = *(const float4*)&B[(size_t)(n0 + row) * K + k0 + lc];
            Bs[lc + 0][row] = vb.x; Bs[lc + 1][row] = vb.y;
            Bs[lc + 2][row] = vb.z; Bs[lc + 3][row] = vb.w;
        }
        __syncthreads();

#pragma unroll
        for (int kk = 0; kk < 16; ++kk) {
            float af[8], bf[8];
            *(float4*)(af)     = *(float4*)&As[kk][ty * 8];
            *(float4*)(af + 4) = *(float4*)&As[kk][ty * 8 + 4];
            *(float4*)(bf)     = *(float4*)&Bs[kk][tx * 8];
            *(float4*)(bf + 4) = *(float4*)&Bs[kk][tx * 8 + 4];
#pragma unroll
            for (int i = 0; i < 8; ++i)
#pragma unroll
                for (int j = 0; j < 8; ++j)
                    acc[i][j] += af[i] * bf[j];
        }
        __syncthreads();
    }

#pragma unroll
    for (int i = 0; i < 8; ++i) {
        float* cp = &C[(size_t)(m0 + ty * 8 + i) * N + n0 + tx * 8];
        *(float4*)(cp)     = make_float4(acc[i][0], acc[i][1], acc[i][2], acc[i][3]);
        *(float4*)(cp + 4) = make_float4(acc[i][4], acc[i][5], acc[i][6], acc[i][7]);
    }
}

// ---------------- RoPE (in place) ----------------
// X: [S, ncols]. Pair (i, i+32) within each 64-wide head, angle = s * 10000^(-i/32).
// Double-precision trig to sidestep any fast-math range-reduction issues.
__global__ void rope_kernel(float* __restrict__ X, int ncols)
{
    int idx = blockIdx.x * blockDim.x + threadIdx.x;
    int pairs_per_row = ncols / 2;
    int total = S_LEN * pairs_per_row;
    if (idx >= total) return;
    int s = idx / pairs_per_row;
    int r = idx - s * pairs_per_row;
    int head = r / 32;
    int i = r - head * 32;

    double inv_freq = pow(10000.0, -(double)i / 32.0);
    double angle = (double)s * inv_freq;
    double cd, sd;
    sincos(angle, &sd, &cd);
    float c = (float)cd, sn = (float)sd;

    size_t base = (size_t)s * ncols + head * 64 + i;
    float x1 = X[base];
    float x2 = X[base + 32];
    X[base]      = x1 * c - x2 * sn;
    X[base + 32] = x2 * c + x1 * sn;
}

// ---------------- Flash attention ----------------
// grid: (S/64 q-blocks, 32 heads), 256 threads as 16x16, 4x4 register tiles.
#define FA_STR 68   // padded row stride (floats), 272B = multiple of 16B

__global__ __launch_bounds__(256) void fa_kernel(
    const float* __restrict__ Q, const float* __restrict__ K,
    const float* __restrict__ V, float* __restrict__ O)
{
    extern __shared__ float sm[];
    float* Qs  = sm;                   // [d][r]  64 x FA_STR
    float* Ks  = sm + 64 * FA_STR;     // [d][c]
    float* Vs  = sm + 2 * 64 * FA_STR; // [j][dim]
    float* PsT = sm + 3 * 64 * FA_STR; // [c][r]

    const int t  = threadIdx.x;
    const int tx = t & 15;
    const int ty = t >> 4;
    const int qb = blockIdx.x;
    const int h  = blockIdx.y;
    const int s0 = qb * 64;
    const int kvh = h / (NHEADS / NKVH);
    const int qcol = h * HDIM;
    const int kcol = kvh * HDIM;
    const float scale = 0.125f;        // 1/sqrt(64)

    for (int idx = t; idx < 64 * 64; idx += 256) {
        int r = idx >> 6, d = idx & 63;
        Qs[d * FA_STR + r] = Q[(size_t)(s0 + r) * DM + qcol + d];
    }

    float o[4][4];
#pragma unroll
    for (int i = 0; i < 4; ++i)
#pragma unroll
        for (int j = 0; j < 4; ++j) o[i][j] = 0.f;
    float mrow[4] = {-INFINITY, -INFINITY, -INFINITY, -INFINITY};
    float lrow[4] = {0.f, 0.f, 0.f, 0.f};

    for (int k0 = 0; k0 < S_LEN; k0 += 64) {
        __syncthreads();
        for (int idx = t; idx < 64 * 64; idx += 256) {
            int c = idx >> 6, d = idx & 63;
            Ks[d * FA_STR + c] = K[(size_t)(k0 + c) * KV_DIM + kcol + d];
            Vs[c * FA_STR + d] = V[(size_t)(k0 + c) * KV_DIM + kcol + d];
        }
        __syncthreads();

        float s[4][4];
#pragma unroll
        for (int i = 0; i < 4; ++i)
#pragma unroll
            for (int j = 0; j < 4; ++j) s[i][j] = 0.f;

#pragma unroll 4
        for (int d = 0; d < 64; ++d) {
            float4 q4 = *(float4*)&Qs[d * FA_STR + ty * 4];
            float4 k4 = *(float4*)&Ks[d * FA_STR + tx * 4];
            float qa[4] = {q4.x, q4.y, q4.z, q4.w};
            float ka[4] = {k4.x, k4.y, k4.z, k4.w};
#pragma unroll
            for (int i = 0; i < 4; ++i)
#pragma unroll
                for (int j = 0; j < 4; ++j)
                    s[i][j] += qa[i] * ka[j];
        }

#pragma unroll
        for (int i = 0; i < 4; ++i) {
            float rmax = -INFINITY;
#pragma unroll
            for (int j = 0; j < 4; ++j) { s[i][j] *= scale; rmax = fmaxf(rmax, s[i][j]); }
#pragma unroll
            for (int w = 1; w < 16; w <<= 1)
                rmax = fmaxf(rmax, __shfl_xor_sync(0xffffffffu, rmax, w));
            float mnew = fmaxf(mrow[i], rmax);
            float alpha = __expf(mrow[i] - mnew);
            float rsum = 0.f;
#pragma unroll
            for (int j = 0; j < 4; ++j) { s[i][j] = __expf(s[i][j] - mnew); rsum += s[i][j]; }
#pragma unroll
            for (int w = 1; w < 16; w <<= 1)
                rsum += __shfl_xor_sync(0xffffffffu, rsum, w);
            lrow[i] = lrow[i] * alpha + rsum;
            mrow[i] = mnew;
#pragma unroll
            for (int j = 0; j < 4; ++j) o[i][j] *= alpha;
        }

#pragma unroll
        for (int j = 0; j < 4; ++j)
            *(float4*)&PsT[(tx * 4 + j) * FA_STR + ty * 4] =
                make_float4(s[0][j], s[1][j], s[2][j], s[3][j]);
        __syncthreads();

#pragma unroll 4
        for (int j64 = 0; j64 < 64; ++j64) {
            float4 p4 = *(float4*)&PsT[j64 * FA_STR + ty * 4];
            float4 v4 = *(float4*)&Vs[j64 * FA_STR + tx * 4];
            float pa[4] = {p4.x, p4.y, p4.z, p4.w};
            float va[4] = {v4.x, v4.y, v4.z, v4.w};
#pragma unroll
            for (int i = 0; i < 4; ++i)
#pragma unroll
                for (int j = 0; j < 4; ++j)
                    o[i][j] += pa[i] * va[j];
        }
    }

#pragma unroll
    for (int i = 0; i < 4; ++i) {
        float inv = 1.0f / lrow[i];
        float4 r = make_float4(o[i][0] * inv, o[i][1] * inv, o[i][2] * inv, o[i][3] * inv);
        *(float4*)&O[(size_t)(s0 + ty * 4 + i) * DM + qcol + tx * 4] = r;
    }
}

// ---------------- launch ----------------
extern "C" void kernel_launch(void* const* d_in, const int* in_sizes, int n_in,
                              void* d_out, int out_size)
{
    // Input-order detection.
    // Hypothesis A (setup_inputs dict order): [x, Wq, Wk, Wv, Wo]
    //   sizes = [4194304, 4194304, 1048576, 1048576, 4194304]
    // Hypothesis B (sorted by name):          [Wk, Wo, Wq, Wv, x]
    //   sizes = [1048576, 4194304, 4194304, 1048576, 4194304]
    const float *x, *Wq, *Wk, *Wv, *Wo;
    if (in_sizes[0] == S_LEN * DM) {
        x  = (const float*)d_in[0];
        Wq = (const float*)d_in[1];
        Wk = (const float*)d_in[2];
        Wv = (const float*)d_in[3];
        Wo = (const float*)d_in[4];
    } else {
        Wk = (const float*)d_in[0];
        Wo = (const float*)d_in[1];
        Wq = (const float*)d_in[2];
        Wv = (const float*)d_in[3];
        x  = (const float*)d_in[4];
    }
    float* out = (float*)d_out;

    float *Qp, *Kp, *Vp, *Ap;
    cudaGetSymbolAddress((void**)&Qp, g_Q);
    cudaGetSymbolAddress((void**)&Kp, g_K);
    cudaGetSymbolAddress((void**)&Vp, g_V);
    cudaGetSymbolAddress((void**)&Ap, g_A);

    // projections
    sgemm_abt<<<dim3(DM / 128, S_LEN / 128), 256>>>(x, Wq, Qp, S_LEN, DM, DM);
    sgemm_abt<<<dim3(KV_DIM / 128, S_LEN / 128), 256>>>(x, Wk, Kp, S_LEN, KV_DIM, DM);
    sgemm_abt<<<dim3(KV_DIM / 128, S_LEN / 128), 256>>>(x, Wv, Vp, S_LEN, KV_DIM, DM);

    // RoPE on Q and K
    {
        int totQ = S_LEN * (DM / 2);
        rope_kernel<<<(totQ + 255) / 256, 256>>>(Qp, DM);
        int totK = S_LEN * (KV_DIM / 2);
        rope_kernel<<<(totK + 255) / 256, 256>>>(Kp, KV_DIM);
    }

    // flash attention
    {
        int smem = 4 * 64 * FA_STR * sizeof(float);  // 69632 B
        cudaFuncSetAttribute(fa_kernel, cudaFuncAttributeMaxDynamicSharedMemorySize, smem);
        fa_kernel<<<dim3(S_LEN / 64, NHEADS), 256, smem>>>(Qp, Kp, Vp, Ap);
    }

    // output projection
    sgemm_abt<<<dim3(DM / 128, S_LEN / 128), 256>>>(Ap, Wo, out, S_LEN, DM, DM);
}

// round 3
// speedup vs baseline: 1.1808x; 1.1808x over previous
#include <cuda_runtime.h>
#include <math.h>

#define S_LEN   2048
#define DM      2048
#define KV_DIM  512
#define NHEADS  32
#define NKVH    8
#define HDIM    64

// ---------------- scratch (allocation-free rule: __device__ globals) ----------------
__device__ float g_Q[S_LEN * DM];     // 16 MB
__device__ float g_K[S_LEN * KV_DIM]; //  4 MB
__device__ float g_V[S_LEN * KV_DIM]; //  4 MB
__device__ float g_A[S_LEN * DM];     // 16 MB (attention output, pre-Wo)
__device__ float g_rc[S_LEN * 32];    // rope cos table
__device__ float g_rs[S_LEN * 32];    // rope sin table

// ---------------- SGEMM: C[M,N] = A[M,K] @ B[N,K]^T ----------------
// BM=BN=128, BK=16, 256 threads, 8x8 per thread, double-buffered smem.
__global__ __launch_bounds__(256) void sgemm_abt(
    const float* __restrict__ A, const float* __restrict__ B,
    float* __restrict__ C, int M, int N, int K)
{
    __shared__ float As[2][16][128];
    __shared__ float Bs[2][16][128];

    const int t  = threadIdx.x;
    const int tx = t & 15;        // n
    const int ty = t >> 4;        // m
    const int m0 = blockIdx.y * 128;
    const int n0 = blockIdx.x * 128;

    const int lr = t >> 2;        // 0..63
    const int lc = (t & 3) * 4;   // 0,4,8,12

    float4 va[2], vb[2];

    // prologue: load tile 0
#pragma unroll
    for (int p = 0; p < 2; ++p) {
        int row = lr + p * 64;
        va[p] = *(const float4*)&A[(size_t)(m0 + row) * K + lc];
        vb[p] = *(const float4*)&B[(size_t)(n0 + row) * K + lc];
    }
#pragma unroll
    for (int p = 0; p < 2; ++p) {
        int row = lr + p * 64;
        As[0][lc + 0][row] = va[p].x; As[0][lc + 1][row] = va[p].y;
        As[0][lc + 2][row] = va[p].z; As[0][lc + 3][row] = va[p].w;
        Bs[0][lc + 0][row] = vb[p].x; Bs[0][lc + 1][row] = vb[p].y;
        Bs[0][lc + 2][row] = vb[p].z; Bs[0][lc + 3][row] = vb[p].w;
    }
    __syncthreads();

    float acc[8][8];
#pragma unroll
    for (int i = 0; i < 8; ++i)
#pragma unroll
        for (int j = 0; j < 8; ++j) acc[i][j] = 0.f;

    const int nt = K / 16;
    for (int tt = 0; tt < nt; ++tt) {
        const int buf = tt & 1;
        // prefetch next tile into registers (overlaps with compute below)
        if (tt + 1 < nt) {
            int k0 = (tt + 1) * 16;
#pragma unroll
            for (int p = 0; p < 2; ++p) {
                int row = lr + p * 64;
                va[p] = *(const float4*)&A[(size_t)(m0 + row) * K + k0 + lc];
                vb[p] = *(const float4*)&B[(size_t)(n0 + row) * K + k0 + lc];
            }
        }

#pragma unroll
        for (int kk = 0; kk < 16; ++kk) {
            float af[8], bf[8];
            *(float4*)(af)     = *(float4*)&As[buf][kk][ty * 8];
            *(float4*)(af + 4) = *(float4*)&As[buf][kk][ty * 8 + 4];
            *(float4*)(bf)     = *(float4*)&Bs[buf][kk][tx * 8];
            *(float4*)(bf + 4) = *(float4*)&Bs[buf][kk][tx * 8 + 4];
#pragma unroll
            for (int i = 0; i < 8; ++i)
#pragma unroll
                for (int j = 0; j < 8; ++j)
                    acc[i][j] += af[i] * bf[j];
        }

        if (tt + 1 < nt) {
            const int nb = buf ^ 1;
#pragma unroll
            for (int p = 0; p < 2; ++p) {
                int row = lr + p * 64;
                As[nb][lc + 0][row] = va[p].x; As[nb][lc + 1][row] = va[p].y;
                As[nb][lc + 2][row] = va[p].z; As[nb][lc + 3][row] = va[p].w;
                Bs[nb][lc + 0][row] = vb[p].x; Bs[nb][lc + 1][row] = vb[p].y;
                Bs[nb][lc + 2][row] = vb[p].z; Bs[nb][lc + 3][row] = vb[p].w;
            }
            __syncthreads();
        }
    }

#pragma unroll
    for (int i = 0; i < 8; ++i) {
        float* cp = &C[(size_t)(m0 + ty * 8 + i) * N + n0 + tx * 8];
        *(float4*)(cp)     = make_float4(acc[i][0], acc[i][1], acc[i][2], acc[i][3]);
        *(float4*)(cp + 4) = make_float4(acc[i][4], acc[i][5], acc[i][6], acc[i][7]);
    }
}

// ---------------- RoPE tables ----------------
// table[s][i] = cos/sin(s * 10000^(-i/32)), fp64 trig once, reused 40x.
__global__ void rope_table(float* __restrict__ rc, float* __restrict__ rs)
{
    int idx = blockIdx.x * blockDim.x + threadIdx.x;
    if (idx >= S_LEN * 32) return;
    int s = idx >> 5;
    int i = idx & 31;
    double ang = (double)s * pow(10000.0, -(double)i / 32.0);
    double sd, cd;
    sincos(ang, &sd, &cd);
    rc[idx] = (float)cd;
    rs[idx] = (float)sd;
}

// Apply RoPE to Q and K in one launch. r in [0,1024): Q pairs, [1024,1280): K pairs.
__global__ void rope_apply_qk(float* __restrict__ Q, float* __restrict__ K,
                              const float* __restrict__ rc, const float* __restrict__ rs)
{
    int idx = blockIdx.x * blockDim.x + threadIdx.x;
    const int per_row = 1280;                  // 1024 Q pairs + 256 K pairs
    if (idx >= S_LEN * per_row) return;
    int s = idx / per_row;
    int r = idx - s * per_row;

    float* X;
    int ncols, rr;
    if (r < 1024) { X = Q; ncols = DM;     rr = r; }
    else          { X = K; ncols = KV_DIM; rr = r - 1024; }
    int head = rr >> 5;
    int i    = rr & 31;

    float c  = rc[(s << 5) + i];
    float sn = rs[(s << 5) + i];

    size_t base = (size_t)s * ncols + head * 64 + i;
    float x1 = X[base];
    float x2 = X[base + 32];
    X[base]      = x1 * c - x2 * sn;
    X[base + 32] = x2 * c + x1 * sn;
}

// ---------------- Flash attention ----------------
// grid: (S/64 q-blocks, 32 heads), 256 threads as 16x16, 4x4 register tiles.
#define FA_STR 68   // padded row stride (floats)

__global__ __launch_bounds__(256) void fa_kernel(
    const float* __restrict__ Q, const float* __restrict__ K,
    const float* __restrict__ V, float* __restrict__ O)
{
    extern __shared__ float sm[];
    float* Qs  = sm;                   // [d][r]  64 x FA_STR
    float* Ks  = sm + 64 * FA_STR;     // [d][c]
    float* Vs  = sm + 2 * 64 * FA_STR; // [j][dim]
    float* PsT = sm + 3 * 64 * FA_STR; // [c][r]

    const int t  = threadIdx.x;
    const int tx = t & 15;
    const int ty = t >> 4;
    const int qb = blockIdx.x;
    const int h  = blockIdx.y;
    const int s0 = qb * 64;
    const int kvh = h / (NHEADS / NKVH);
    const int qcol = h * HDIM;
    const int kcol = kvh * HDIM;
    const float scale = 0.125f;        // 1/sqrt(64)

    for (int idx = t; idx < 64 * 64; idx += 256) {
        int r = idx >> 6, d = idx & 63;
        Qs[d * FA_STR + r] = Q[(size_t)(s0 + r) * DM + qcol + d];
    }

    float o[4][4];
#pragma unroll
    for (int i = 0; i < 4; ++i)
#pragma unroll
        for (int j = 0; j < 4; ++j) o[i][j] = 0.f;
    float mrow[4] = {-INFINITY, -INFINITY, -INFINITY, -INFINITY};
    float lrow[4] = {0.f, 0.f, 0.f, 0.f};

    for (int k0 = 0; k0 < S_LEN; k0 += 64) {
        __syncthreads();
        for (int idx = t; idx < 64 * 64; idx += 256) {
            int c = idx >> 6, d = idx & 63;
            Ks[d * FA_STR + c] = K[(size_t)(k0 + c) * KV_DIM + kcol + d];
            Vs[c * FA_STR + d] = V[(size_t)(k0 + c) * KV_DIM + kcol + d];
        }
        __syncthreads();

        float s[4][4];
#pragma unroll
        for (int i = 0; i < 4; ++i)
#pragma unroll
            for (int j = 0; j < 4; ++j) s[i][j] = 0.f;

#pragma unroll 4
        for (int d = 0; d < 64; ++d) {
            float4 q4 = *(float4*)&Qs[d * FA_STR + ty * 4];
            float4 k4 = *(float4*)&Ks[d * FA_STR + tx * 4];
            float qa[4] = {q4.x, q4.y, q4.z, q4.w};
            float ka[4] = {k4.x, k4.y, k4.z, k4.w};
#pragma unroll
            for (int i = 0; i < 4; ++i)
#pragma unroll
                for (int j = 0; j < 4; ++j)
                    s[i][j] += qa[i] * ka[j];
        }

#pragma unroll
        for (int i = 0; i < 4; ++i) {
            float rmax = -INFINITY;
#pragma unroll
            for (int j = 0; j < 4; ++j) { s[i][j] *= scale; rmax = fmaxf(rmax, s[i][j]); }
#pragma unroll
            for (int w = 1; w < 16; w <<= 1)
                rmax = fmaxf(rmax, __shfl_xor_sync(0xffffffffu, rmax, w));
            float mnew = fmaxf(mrow[i], rmax);
            float alpha = __expf(mrow[i] - mnew);
            float rsum = 0.f;
#pragma unroll
            for (int j = 0; j < 4; ++j) { s[i][j] = __expf(s[i][j] - mnew); rsum += s[i][j]; }
#pragma unroll
            for (int w = 1; w < 16; w <<= 1)
                rsum += __shfl_xor_sync(0xffffffffu, rsum, w);
            lrow[i] = lrow[i] * alpha + rsum;
            mrow[i] = mnew;
#pragma unroll
            for (int j = 0; j < 4; ++j) o[i][j] *= alpha;
        }

#pragma unroll
        for (int j = 0; j < 4; ++j)
            *(float4*)&PsT[(tx * 4 + j) * FA_STR + ty * 4] =
                make_float4(s[0][j], s[1][j], s[2][j], s[3][j]);
        __syncthreads();

#pragma unroll 4
        for (int j64 = 0; j64 < 64; ++j64) {
            float4 p4 = *(float4*)&PsT[j64 * FA_STR + ty * 4];
            float4 v4 = *(float4*)&Vs[j64 * FA_STR + tx * 4];
            float pa[4] = {p4.x, p4.y, p4.z, p4.w};
            float va[4] = {v4.x, v4.y, v4.z, v4.w};
#pragma unroll
            for (int i = 0; i < 4; ++i)
#pragma unroll
                for (int j = 0; j < 4; ++j)
                    o[i][j] += pa[i] * va[j];
        }
    }

#pragma unroll
    for (int i = 0; i < 4; ++i) {
        float inv = 1.0f / lrow[i];
        float4 r = make_float4(o[i][0] * inv, o[i][1] * inv, o[i][2] * inv, o[i][3] * inv);
        *(float4*)&O[(size_t)(s0 + ty * 4 + i) * DM + qcol + tx * 4] = r;
    }
}

// ---------------- launch ----------------
extern "C" void kernel_launch(void* const* d_in, const int* in_sizes, int n_in,
                              void* d_out, int out_size)
{
    // Input-order detection:
    //   dict order:   [x, Wq, Wk, Wv, Wo]  -> in_sizes[0] == 2048*2048
    //   sorted order: [Wk, Wo, Wq, Wv, x]  -> in_sizes[0] == 512*2048
    const float *x, *Wq, *Wk, *Wv, *Wo;
    if (in_sizes[0] == S_LEN * DM) {
        x  = (const float*)d_in[0];
        Wq = (const float*)d_in[1];
        Wk = (const float*)d_in[2];
        Wv = (const float*)d_in[3];
        Wo = (const float*)d_in[4];
    } else {
        Wk = (const float*)d_in[0];
        Wo = (const float*)d_in[1];
        Wq = (const float*)d_in[2];
        Wv = (const float*)d_in[3];
        x  = (const float*)d_in[4];
    }
    float* out = (float*)d_out;

    float *Qp, *Kp, *Vp, *Ap, *rc, *rs;
    cudaGetSymbolAddress((void**)&Qp, g_Q);
    cudaGetSymbolAddress((void**)&Kp, g_K);
    cudaGetSymbolAddress((void**)&Vp, g_V);
    cudaGetSymbolAddress((void**)&Ap, g_A);
    cudaGetSymbolAddress((void**)&rc, g_rc);
    cudaGetSymbolAddress((void**)&rs, g_rs);

    // 1-3: projections
    sgemm_abt<<<dim3(DM / 128, S_LEN / 128), 256>>>(x, Wq, Qp, S_LEN, DM, DM);
    sgemm_abt<<<dim3(KV_DIM / 128, S_LEN / 128), 256>>>(x, Wk, Kp, S_LEN, KV_DIM, DM);
    sgemm_abt<<<dim3(KV_DIM / 128, S_LEN / 128), 256>>>(x, Wv, Vp, S_LEN, KV_DIM, DM);

    // 4: rope tables   5: apply to Q+K
    rope_table<<<(S_LEN * 32 + 255) / 256, 256>>>(rc, rs);
    rope_apply_qk<<<(S_LEN * 1280 + 255) / 256, 256>>>(Qp, Kp, rc, rs);

    // 6: flash attention (profiled launch under -s 5 -c 1)
    {
        int smem = 4 * 64 * FA_STR * sizeof(float);  // 69632 B
        cudaFuncSetAttribute(fa_kernel, cudaFuncAttributeMaxDynamicSharedMemorySize, smem);
        fa_kernel<<<dim3(S_LEN / 64, NHEADS), 256, smem>>>(Qp, Kp, Vp, Ap);
    }

    // 7: output projection
    sgemm_abt<<<dim3(DM / 128, S_LEN / 128), 256>>>(Ap, Wo, out, S_LEN, DM, DM);
}

// round 4
// speedup vs baseline: 1.2448x; 1.0542x over previous
#include <cuda_runtime.h>
#include <math.h>
#include <stdint.h>

#define S_LEN   2048
#define DM      2048
#define KV_DIM  512
#define NHEADS  32
#define NKVH    8
#define HDIM    64

// ---------------- scratch ----------------
__device__ float g_Q[S_LEN * DM];
__device__ float g_K[S_LEN * KV_DIM];
__device__ float g_V[S_LEN * KV_DIM];
__device__ float g_A[S_LEN * DM];
__device__ float g_rc[S_LEN * 32];
__device__ float g_rs[S_LEN * 32];

// ---------------- tf32 helpers ----------------
__device__ __forceinline__ uint32_t f2tf32(float f) {
    uint32_t u;
    asm("cvt.rna.tf32.f32 %0, %1;" : "=r"(u) : "f"(f));
    return u;
}

__device__ __forceinline__ void mma_tf32(float* c, const uint32_t* a, const uint32_t* b) {
    asm volatile(
        "mma.sync.aligned.m16n8k8.row.col.f32.tf32.tf32.f32 "
        "{%0,%1,%2,%3}, {%4,%5,%6,%7}, {%8,%9}, {%0,%1,%2,%3};"
        : "+f"(c[0]), "+f"(c[1]), "+f"(c[2]), "+f"(c[3])
        : "r"(a[0]), "r"(a[1]), "r"(a[2]), "r"(a[3]), "r"(b[0]), "r"(b[1]));
}

__device__ __forceinline__ void ldsm4(uint32_t* r, uint32_t addr) {
    asm volatile("ldmatrix.sync.aligned.m8n8.x4.shared.b16 {%0,%1,%2,%3}, [%4];"
        : "=r"(r[0]), "=r"(r[1]), "=r"(r[2]), "=r"(r[3]) : "r"(addr));
}

// ---------------- tf32x3 GEMM: C[M,N] = A[M,K] @ B[N,K]^T ----------------
// BM=BN=128, BK=32, 256 threads (8 warps, 4m x 2n), warp tile 32x64.
#define BK 32
#define KSTR 36   // padded floats per smem row (conflict-free ldmatrix)

__global__ __launch_bounds__(256) void gemm_tf32x3(
    const float* __restrict__ A, const float* __restrict__ B,
    float* __restrict__ C, int M, int N, int K)
{
    extern __shared__ float smx[];
    float* As[2] = { smx,                 smx + 2 * 128 * KSTR };
    float* Bs[2] = { smx + 128 * KSTR,    smx + 3 * 128 * KSTR };

    const int t    = threadIdx.x;
    const int lane = t & 31;
    const int warp = t >> 5;
    const int wm   = warp >> 1;   // 0..3
    const int wn   = warp & 1;    // 0..1
    const int m0   = blockIdx.y * 128;
    const int n0   = blockIdx.x * 128;

    // gmem load assignment: 2 threads per row, 16 floats each
    const int lrow = t >> 1;           // 0..127
    const int lcb  = (t & 1) * 16;     // 0 or 16

    // ldmatrix per-lane offsets (bytes) within tile
    const int g  = lane >> 3;
    const int r8 = lane & 7;
    const int aOff = ((wm * 32 + (g & 1) * 8 + r8) * KSTR + (g >> 1) * 4) * 4;
    const int bOff = ((wn * 64 + (g >> 1) * 8 + r8) * KSTR + (g & 1) * 4) * 4;

    uint32_t aBase[2], bBase[2];
    aBase[0] = (uint32_t)__cvta_generic_to_shared(As[0]);
    aBase[1] = (uint32_t)__cvta_generic_to_shared(As[1]);
    bBase[0] = (uint32_t)__cvta_generic_to_shared(Bs[0]);
    bBase[1] = (uint32_t)__cvta_generic_to_shared(Bs[1]);

    float acc[2][8][4];
#pragma unroll
    for (int i = 0; i < 2; ++i)
#pragma unroll
        for (int j = 0; j < 8; ++j)
#pragma unroll
            for (int k = 0; k < 4; ++k) acc[i][j][k] = 0.f;

    float4 pa[4], pb[4];
    // prologue: tile 0
#pragma unroll
    for (int i = 0; i < 4; ++i) {
        pa[i] = *(const float4*)&A[(size_t)(m0 + lrow) * K + lcb + i * 4];
        pb[i] = *(const float4*)&B[(size_t)(n0 + lrow) * K + lcb + i * 4];
    }
#pragma unroll
    for (int i = 0; i < 4; ++i) {
        *(float4*)&As[0][lrow * KSTR + lcb + i * 4] = pa[i];
        *(float4*)&Bs[0][lrow * KSTR + lcb + i * 4] = pb[i];
    }
    __syncthreads();

    const int nt = K / BK;
    for (int tt = 0; tt < nt; ++tt) {
        const int buf = tt & 1;
        if (tt + 1 < nt) {
            const int k0 = (tt + 1) * BK;
#pragma unroll
            for (int i = 0; i < 4; ++i) {
                pa[i] = *(const float4*)&A[(size_t)(m0 + lrow) * K + k0 + lcb + i * 4];
                pb[i] = *(const float4*)&B[(size_t)(n0 + lrow) * K + k0 + lcb + i * 4];
            }
        }

#pragma unroll
        for (int ks = 0; ks < BK / 8; ++ks) {
            const int kb = ks * 8 * 4;  // byte offset for kbase
            // A fragments (2 m16 tiles), raw then split hi/lo
            uint32_t ahi[2][4], alo[2][4];
#pragma unroll
            for (int im = 0; im < 2; ++im) {
                uint32_t araw[4];
                ldsm4(araw, aBase[buf] + aOff + im * 16 * KSTR * 4 + kb);
#pragma unroll
                for (int p = 0; p < 4; ++p) {
                    float v = __uint_as_float(araw[p]);
                    uint32_t h = f2tf32(v);
                    ahi[im][p] = h;
                    alo[im][p] = f2tf32(v - __uint_as_float(h));
                }
            }
#pragma unroll
            for (int jn = 0; jn < 4; ++jn) {   // pairs of n8 tiles
                uint32_t braw[4], bhi[4], blo[4];
                ldsm4(braw, bBase[buf] + bOff + jn * 16 * KSTR * 4 + kb);
#pragma unroll
                for (int p = 0; p < 4; ++p) {
                    float v = __uint_as_float(braw[p]);
                    uint32_t h = f2tf32(v);
                    bhi[p] = h;
                    blo[p] = f2tf32(v - __uint_as_float(h));
                }
#pragma unroll
                for (int jt = 0; jt < 2; ++jt) {
                    const int ntile = jn * 2 + jt;
#pragma unroll
                    for (int im = 0; im < 2; ++im) {
                        mma_tf32(acc[im][ntile], alo[im], bhi + jt * 2);
                        mma_tf32(acc[im][ntile], ahi[im], blo + jt * 2);
                        mma_tf32(acc[im][ntile], ahi[im], bhi + jt * 2);
                    }
                }
            }
        }

        if (tt + 1 < nt) {
            const int nb = buf ^ 1;
#pragma unroll
            for (int i = 0; i < 4; ++i) {
                *(float4*)&As[nb][lrow * KSTR + lcb + i * 4] = pa[i];
                *(float4*)&Bs[nb][lrow * KSTR + lcb + i * 4] = pb[i];
            }
            __syncthreads();
        }
    }

    // epilogue
    const int crow0 = m0 + wm * 32 + (lane >> 2);
    const int ccol0 = n0 + wn * 64 + (lane & 3) * 2;
#pragma unroll
    for (int im = 0; im < 2; ++im) {
#pragma unroll
        for (int nt2 = 0; nt2 < 8; ++nt2) {
            const int row = crow0 + im * 16;
            const int col = ccol0 + nt2 * 8;
            *(float2*)&C[(size_t)row * N + col] =
                make_float2(acc[im][nt2][0], acc[im][nt2][1]);
            *(float2*)&C[(size_t)(row + 8) * N + col] =
                make_float2(acc[im][nt2][2], acc[im][nt2][3]);
        }
    }
}

// ---------------- RoPE tables + apply ----------------
__global__ void rope_table(float* __restrict__ rc, float* __restrict__ rs)
{
    int idx = blockIdx.x * blockDim.x + threadIdx.x;
    if (idx >= S_LEN * 32) return;
    int s = idx >> 5;
    int i = idx & 31;
    double ang = (double)s * pow(10000.0, -(double)i / 32.0);
    double sd, cd;
    sincos(ang, &sd, &cd);
    rc[idx] = (float)cd;
    rs[idx] = (float)sd;
}

__global__ void rope_apply_qk(float* __restrict__ Q, float* __restrict__ K,
                              const float* __restrict__ rc, const float* __restrict__ rs)
{
    int idx = blockIdx.x * blockDim.x + threadIdx.x;
    const int per_row = 1280;
    if (idx >= S_LEN * per_row) return;
    int s = idx / per_row;
    int r = idx - s * per_row;

    float* X;
    int ncols, rr;
    if (r < 1024) { X = Q; ncols = DM;     rr = r; }
    else          { X = K; ncols = KV_DIM; rr = r - 1024; }
    int head = rr >> 5;
    int i    = rr & 31;

    float c  = rc[(s << 5) + i];
    float sn = rs[(s << 5) + i];

    size_t base = (size_t)s * ncols + head * 64 + i;
    float x1 = X[base];
    float x2 = X[base + 32];
    X[base]      = x1 * c - x2 * sn;
    X[base + 32] = x2 * c + x1 * sn;
}

// ---------------- Flash attention (fp32, unchanged) ----------------
#define FA_STR 68

__global__ __launch_bounds__(256) void fa_kernel(
    const float* __restrict__ Q, const float* __restrict__ K,
    const float* __restrict__ V, float* __restrict__ O)
{
    extern __shared__ float sm[];
    float* Qs  = sm;
    float* Ks  = sm + 64 * FA_STR;
    float* Vs  = sm + 2 * 64 * FA_STR;
    float* PsT = sm + 3 * 64 * FA_STR;

    const int t  = threadIdx.x;
    const int tx = t & 15;
    const int ty = t >> 4;
    const int qb = blockIdx.x;
    const int h  = blockIdx.y;
    const int s0 = qb * 64;
    const int kvh = h / (NHEADS / NKVH);
    const int qcol = h * HDIM;
    const int kcol = kvh * HDIM;
    const float scale = 0.125f;

    for (int idx = t; idx < 64 * 64; idx += 256) {
        int r = idx >> 6, d = idx & 63;
        Qs[d * FA_STR + r] = Q[(size_t)(s0 + r) * DM + qcol + d];
    }

    float o[4][4];
#pragma unroll
    for (int i = 0; i < 4; ++i)
#pragma unroll
        for (int j = 0; j < 4; ++j) o[i][j] = 0.f;
    float mrow[4] = {-INFINITY, -INFINITY, -INFINITY, -INFINITY};
    float lrow[4] = {0.f, 0.f, 0.f, 0.f};

    for (int k0 = 0; k0 < S_LEN; k0 += 64) {
        __syncthreads();
        for (int idx = t; idx < 64 * 64; idx += 256) {
            int c = idx >> 6, d = idx & 63;
            Ks[d * FA_STR + c] = K[(size_t)(k0 + c) * KV_DIM + kcol + d];
            Vs[c * FA_STR + d] = V[(size_t)(k0 + c) * KV_DIM + kcol + d];
        }
        __syncthreads();

        float s[4][4];
#pragma unroll
        for (int i = 0; i < 4; ++i)
#pragma unroll
            for (int j = 0; j < 4; ++j) s[i][j] = 0.f;

#pragma unroll 4
        for (int d = 0; d < 64; ++d) {
            float4 q4 = *(float4*)&Qs[d * FA_STR + ty * 4];
            float4 k4 = *(float4*)&Ks[d * FA_STR + tx * 4];
            float qa[4] = {q4.x, q4.y, q4.z, q4.w};
            float ka[4] = {k4.x, k4.y, k4.z, k4.w};
#pragma unroll
            for (int i = 0; i < 4; ++i)
#pragma unroll
                for (int j = 0; j < 4; ++j)
                    s[i][j] += qa[i] * ka[j];
        }

#pragma unroll
        for (int i = 0; i < 4; ++i) {
            float rmax = -INFINITY;
#pragma unroll
            for (int j = 0; j < 4; ++j) { s[i][j] *= scale; rmax = fmaxf(rmax, s[i][j]); }
#pragma unroll
            for (int w = 1; w < 16; w <<= 1)
                rmax = fmaxf(rmax, __shfl_xor_sync(0xffffffffu, rmax, w));
            float mnew = fmaxf(mrow[i], rmax);
            float alpha = __expf(mrow[i] - mnew);
            float rsum = 0.f;
#pragma unroll
            for (int j = 0; j < 4; ++j) { s[i][j] = __expf(s[i][j] - mnew); rsum += s[i][j]; }
#pragma unroll
            for (int w = 1; w < 16; w <<= 1)
                rsum += __shfl_xor_sync(0xffffffffu, rsum, w);
            lrow[i] = lrow[i] * alpha + rsum;
            mrow[i] = mnew;
#pragma unroll
            for (int j = 0; j < 4; ++j) o[i][j] *= alpha;
        }

#pragma unroll
        for (int j = 0; j < 4; ++j)
            *(float4*)&PsT[(tx * 4 + j) * FA_STR + ty * 4] =
                make_float4(s[0][j], s[1][j], s[2][j], s[3][j]);
        __syncthreads();

#pragma unroll 4
        for (int j64 = 0; j64 < 64; ++j64) {
            float4 p4 = *(float4*)&PsT[j64 * FA_STR + ty * 4];
            float4 v4 = *(float4*)&Vs[j64 * FA_STR + tx * 4];
            float pa[4] = {p4.x, p4.y, p4.z, p4.w};
            float va[4] = {v4.x, v4.y, v4.z, v4.w};
#pragma unroll
            for (int i = 0; i < 4; ++i)
#pragma unroll
                for (int j = 0; j < 4; ++j)
                    o[i][j] += pa[i] * va[j];
        }
    }

#pragma unroll
    for (int i = 0; i < 4; ++i) {
        float inv = 1.0f / lrow[i];
        float4 r = make_float4(o[i][0] * inv, o[i][1] * inv, o[i][2] * inv, o[i][3] * inv);
        *(float4*)&O[(size_t)(s0 + ty * 4 + i) * DM + qcol + tx * 4] = r;
    }
}

// ---------------- launch ----------------
extern "C" void kernel_launch(void* const* d_in, const int* in_sizes, int n_in,
                              void* d_out, int out_size)
{
    const float *x, *Wq, *Wk, *Wv, *Wo;
    if (in_sizes[0] == S_LEN * DM) {        // dict order [x, Wq, Wk, Wv, Wo]
        x  = (const float*)d_in[0];
        Wq = (const float*)d_in[1];
        Wk = (const float*)d_in[2];
        Wv = (const float*)d_in[3];
        Wo = (const float*)d_in[4];
    } else {                                 // sorted order [Wk, Wo, Wq, Wv, x]
        Wk = (const float*)d_in[0];
        Wo = (const float*)d_in[1];
        Wq = (const float*)d_in[2];
        Wv = (const float*)d_in[3];
        x  = (const float*)d_in[4];
    }
    float* out = (float*)d_out;

    float *Qp, *Kp, *Vp, *Ap, *rc, *rs;
    cudaGetSymbolAddress((void**)&Qp, g_Q);
    cudaGetSymbolAddress((void**)&Kp, g_K);
    cudaGetSymbolAddress((void**)&Vp, g_V);
    cudaGetSymbolAddress((void**)&Ap, g_A);
    cudaGetSymbolAddress((void**)&rc, g_rc);
    cudaGetSymbolAddress((void**)&rs, g_rs);

    const int gemm_smem = 4 * 128 * KSTR * sizeof(float);  // 73728 B
    cudaFuncSetAttribute(gemm_tf32x3, cudaFuncAttributeMaxDynamicSharedMemorySize, gemm_smem);

    // 1-3: projections (tensor cores, tf32x3)
    gemm_tf32x3<<<dim3(DM / 128, S_LEN / 128), 256, gemm_smem>>>(x, Wq, Qp, S_LEN, DM, DM);
    gemm_tf32x3<<<dim3(KV_DIM / 128, S_LEN / 128), 256, gemm_smem>>>(x, Wk, Kp, S_LEN, KV_DIM, DM);
    gemm_tf32x3<<<dim3(KV_DIM / 128, S_LEN / 128), 256, gemm_smem>>>(x, Wv, Vp, S_LEN, KV_DIM, DM);

    // 4-5: RoPE
    rope_table<<<(S_LEN * 32 + 255) / 256, 256>>>(rc, rs);
    rope_apply_qk<<<(S_LEN * 1280 + 255) / 256, 256>>>(Qp, Kp, rc, rs);

    // 6: flash attention (profiled launch)
    {
        int smem = 4 * 64 * FA_STR * sizeof(float);
        cudaFuncSetAttribute(fa_kernel, cudaFuncAttributeMaxDynamicSharedMemorySize, smem);
        fa_kernel<<<dim3(S_LEN / 64, NHEADS), 256, smem>>>(Qp, Kp, Vp, Ap);
    }

    // 7: output projection
    gemm_tf32x3<<<dim3(DM / 128, S_LEN / 128), 256, gemm_smem>>>(Ap, Wo, out, S_LEN, DM, DM);
}

// round 5
// speedup vs baseline: 2.1728x; 1.7455x over previous
#include <cuda_runtime.h>
#include <cuda_bf16.h>
#include <math.h>
#include <stdint.h>

#define S_LEN   2048
#define DM      2048
#define KV_DIM  512
#define NHEADS  32
#define NKVH    8
#define HDIM    64

// ---------------- scratch ----------------
__device__ float g_Q[S_LEN * DM];
__device__ float g_K[S_LEN * KV_DIM];
__device__ float g_V[S_LEN * KV_DIM];
__device__ float g_A[S_LEN * DM];
__device__ float g_rc[S_LEN * 32];
__device__ float g_rs[S_LEN * 32];

// ---------------- bf16 helpers ----------------
// pack two floats as bf16x2: elem0 -> low 16 bits, elem1 -> high.
__device__ __forceinline__ uint32_t pack_bf16x2(float e0, float e1) {
    uint32_t u;
    asm("cvt.rn.bf16x2.f32 %0, %1, %2;" : "=r"(u) : "f"(e1), "f"(e0));
    return u;
}

// split pair (x0,x1) into hi/lo packed bf16x2
__device__ __forceinline__ void split_pair(float x0, float x1, uint32_t& h, uint32_t& l) {
    float h0 = __bfloat162float(__float2bfloat16(x0));
    float h1 = __bfloat162float(__float2bfloat16(x1));
    h = pack_bf16x2(h0, h1);
    l = pack_bf16x2(x0 - h0, x1 - h1);
}

__device__ __forceinline__ void mma_bf16(float* c, const uint32_t* a, const uint32_t* b) {
    asm volatile(
        "mma.sync.aligned.m16n8k16.row.col.f32.bf16.bf16.f32 "
        "{%0,%1,%2,%3}, {%4,%5,%6,%7}, {%8,%9}, {%0,%1,%2,%3};"
        : "+f"(c[0]), "+f"(c[1]), "+f"(c[2]), "+f"(c[3])
        : "r"(a[0]), "r"(a[1]), "r"(a[2]), "r"(a[3]), "r"(b[0]), "r"(b[1]));
}

// ---------------- bf16x3 GEMM: C[M,N] = A[M,K] @ B[N,K]^T ----------------
// BM=BN=128, BK=32, 256 threads (8 warps: 4m x 2n), warp tile 32x64.
// smem per buffer: aHi|aLo|bHi|bLo, each 128 rows x GSTR uints (uint = bf16 pair).
#define GBK  32
#define GSTR 20   // uints per row (16 used + 4 pad) -> conflict-free frag loads

__global__ __launch_bounds__(256) void gemm_bf16x3(
    const float* __restrict__ A, const float* __restrict__ B,
    float* __restrict__ C, int M, int N, int K)
{
    extern __shared__ uint32_t gsm[];
    const int TILE = 128 * GSTR;      // 2560 uints

    const int t    = threadIdx.x;
    const int lane = t & 31;
    const int warp = t >> 5;
    const int wm   = warp >> 1;
    const int wn   = warp & 1;
    const int m0   = blockIdx.y * 128;
    const int n0   = blockIdx.x * 128;

    const int lrow = t >> 1;          // 0..127
    const int lcb  = (t & 1) * 16;    // float col base: 0 or 16

    float acc[2][8][4];
#pragma unroll
    for (int i = 0; i < 2; ++i)
#pragma unroll
        for (int j = 0; j < 8; ++j)
#pragma unroll
            for (int k = 0; k < 4; ++k) acc[i][j][k] = 0.f;

    float4 pa[4], pb[4];

    // prologue: tile 0
#pragma unroll
    for (int i = 0; i < 4; ++i) {
        pa[i] = *(const float4*)&A[(size_t)(m0 + lrow) * K + lcb + i * 4];
        pb[i] = *(const float4*)&B[(size_t)(n0 + lrow) * K + lcb + i * 4];
    }
    {
        uint32_t* aHi = gsm;              uint32_t* aLo = gsm + TILE;
        uint32_t* bHi = gsm + 2 * TILE;   uint32_t* bLo = gsm + 3 * TILE;
        const float* fa = (const float*)pa;
        const float* fb = (const float*)pb;
#pragma unroll
        for (int j = 0; j < 8; ++j) {
            uint32_t h, l;
            split_pair(fa[2 * j], fa[2 * j + 1], h, l);
            aHi[lrow * GSTR + lcb / 2 + j] = h;
            aLo[lrow * GSTR + lcb / 2 + j] = l;
            split_pair(fb[2 * j], fb[2 * j + 1], h, l);
            bHi[lrow * GSTR + lcb / 2 + j] = h;
            bLo[lrow * GSTR + lcb / 2 + j] = l;
        }
    }
    __syncthreads();

    const int r4 = lane >> 2;   // 0..7
    const int c4 = lane & 3;    // 0..3

    const int nt = K / GBK;
    for (int tt = 0; tt < nt; ++tt) {
        const int buf = tt & 1;
        uint32_t* aHi = gsm + buf * 4 * TILE;
        uint32_t* aLo = aHi + TILE;
        uint32_t* bHi = aHi + 2 * TILE;
        uint32_t* bLo = aHi + 3 * TILE;

        if (tt + 1 < nt) {
            const int k0 = (tt + 1) * GBK;
#pragma unroll
            for (int i = 0; i < 4; ++i) {
                pa[i] = *(const float4*)&A[(size_t)(m0 + lrow) * K + k0 + lcb + i * 4];
                pb[i] = *(const float4*)&B[(size_t)(n0 + lrow) * K + k0 + lcb + i * 4];
            }
        }

#pragma unroll
        for (int g = 0; g < 2; ++g) {           // two k16 groups
            uint32_t ah[2][4], al[2][4];
#pragma unroll
            for (int im = 0; im < 2; ++im) {
                const int aidx = (wm * 32 + im * 16 + r4) * GSTR + g * 8 + c4;
                ah[im][0] = aHi[aidx];
                ah[im][1] = aHi[aidx + 8 * GSTR];
                ah[im][2] = aHi[aidx + 4];
                ah[im][3] = aHi[aidx + 8 * GSTR + 4];
                al[im][0] = aLo[aidx];
                al[im][1] = aLo[aidx + 8 * GSTR];
                al[im][2] = aLo[aidx + 4];
                al[im][3] = aLo[aidx + 8 * GSTR + 4];
            }
#pragma unroll
            for (int jn = 0; jn < 8; ++jn) {
                const int bidx = (wn * 64 + jn * 8 + r4) * GSTR + g * 8 + c4;
                uint32_t bh[2], bl[2];
                bh[0] = bHi[bidx]; bh[1] = bHi[bidx + 4];
                bl[0] = bLo[bidx]; bl[1] = bLo[bidx + 4];
#pragma unroll
                for (int im = 0; im < 2; ++im) {
                    mma_bf16(acc[im][jn], al[im], bh);
                    mma_bf16(acc[im][jn], ah[im], bl);
                    mma_bf16(acc[im][jn], ah[im], bh);
                }
            }
        }

        if (tt + 1 < nt) {
            const int nb = buf ^ 1;
            uint32_t* naHi = gsm + nb * 4 * TILE;
            uint32_t* naLo = naHi + TILE;
            uint32_t* nbHi = naHi + 2 * TILE;
            uint32_t* nbLo = naHi + 3 * TILE;
            const float* fa = (const float*)pa;
            const float* fb = (const float*)pb;
#pragma unroll
            for (int j = 0; j < 8; ++j) {
                uint32_t h, l;
                split_pair(fa[2 * j], fa[2 * j + 1], h, l);
                naHi[lrow * GSTR + lcb / 2 + j] = h;
                naLo[lrow * GSTR + lcb / 2 + j] = l;
                split_pair(fb[2 * j], fb[2 * j + 1], h, l);
                nbHi[lrow * GSTR + lcb / 2 + j] = h;
                nbLo[lrow * GSTR + lcb / 2 + j] = l;
            }
            __syncthreads();
        }
    }

    // epilogue (m16n8k16 C fragment layout)
    const int crow0 = m0 + wm * 32 + r4;
    const int ccol0 = n0 + wn * 64 + c4 * 2;
#pragma unroll
    for (int im = 0; im < 2; ++im) {
#pragma unroll
        for (int jn = 0; jn < 8; ++jn) {
            const int row = crow0 + im * 16;
            const int col = ccol0 + jn * 8;
            *(float2*)&C[(size_t)row * N + col] =
                make_float2(acc[im][jn][0], acc[im][jn][1]);
            *(float2*)&C[(size_t)(row + 8) * N + col] =
                make_float2(acc[im][jn][2], acc[im][jn][3]);
        }
    }
}

// ---------------- RoPE ----------------
__global__ void rope_table(float* __restrict__ rc, float* __restrict__ rs)
{
    int idx = blockIdx.x * blockDim.x + threadIdx.x;
    if (idx >= S_LEN * 32) return;
    int s = idx >> 5;
    int i = idx & 31;
    double ang = (double)s * pow(10000.0, -(double)i / 32.0);
    double sd, cd;
    sincos(ang, &sd, &cd);
    rc[idx] = (float)cd;
    rs[idx] = (float)sd;
}

__global__ void rope_apply_qk(float* __restrict__ Q, float* __restrict__ K,
                              const float* __restrict__ rc, const float* __restrict__ rs)
{
    int idx = blockIdx.x * blockDim.x + threadIdx.x;
    const int per_row = 1280;
    if (idx >= S_LEN * per_row) return;
    int s = idx / per_row;
    int r = idx - s * per_row;

    float* X;
    int ncols, rr;
    if (r < 1024) { X = Q; ncols = DM;     rr = r; }
    else          { X = K; ncols = KV_DIM; rr = r - 1024; }
    int head = rr >> 5;
    int i    = rr & 31;

    float c  = rc[(s << 5) + i];
    float sn = rs[(s << 5) + i];

    size_t base = (size_t)s * ncols + head * 64 + i;
    float x1 = X[base];
    float x2 = X[base + 32];
    X[base]      = x1 * c - x2 * sn;
    X[base + 32] = x2 * c + x1 * sn;
}

// ---------------- Flash attention, tensor-core bf16x3 ----------------
// grid (16 q-blocks, 32 heads), 256 threads = 8 warps x 16 q-rows.
// Tiles: Q 128x64, KV tile 64. smem uint strides FSTR=36 (72 bf16, pad 8).
#define FSTR 36

__global__ __launch_bounds__(256) void fa_tc(
    const float* __restrict__ Q, const float* __restrict__ K,
    const float* __restrict__ V, float* __restrict__ O)
{
    extern __shared__ uint32_t fsm[];
    uint32_t* Qh = fsm;                       // 128*36
    uint32_t* Ql = Qh + 128 * FSTR;
    uint32_t* Kh = Ql + 128 * FSTR;           // 64*36
    uint32_t* Kl = Kh + 64 * FSTR;
    uint32_t* Vh = Kl + 64 * FSTR;            // V^T: [d][j], 64*36
    uint32_t* Vl = Vh + 64 * FSTR;

    const int t    = threadIdx.x;
    const int lane = t & 31;
    const int warp = t >> 5;
    const int r4   = lane >> 2;
    const int c4   = lane & 3;
    const int qb   = blockIdx.x;
    const int h    = blockIdx.y;
    const int s0   = qb * 128;
    const int kvh  = h / (NHEADS / NKVH);
    const int qcol = h * HDIM;
    const int kcol = kvh * HDIM;
    const float scale = 0.125f;

    // ---- load Q tile (scaled) : row = t>>1, 32 floats at (t&1)*32 ----
    {
        const int row  = t >> 1;
        const int half = (t & 1) * 32;
        const float* src = &Q[(size_t)(s0 + row) * DM + qcol + half];
#pragma unroll
        for (int j = 0; j < 16; ++j) {
            float x0 = src[2 * j]     * scale;
            float x1 = src[2 * j + 1] * scale;
            uint32_t hh, ll;
            split_pair(x0, x1, hh, ll);
            Qh[row * FSTR + half / 2 + j] = hh;
            Ql[row * FSTR + half / 2 + j] = ll;
        }
    }

    float o[8][4];
#pragma unroll
    for (int j = 0; j < 8; ++j)
#pragma unroll
        for (int k = 0; k < 4; ++k) o[j][k] = 0.f;
    float mrow[2] = {-INFINITY, -INFINITY};
    float lrow[2] = {0.f, 0.f};

    for (int k0 = 0; k0 < S_LEN; k0 += 64) {
        __syncthreads();   // prior iteration fully consumed smem

        // ---- K tile: row c = t>>2, 16 floats at (t&3)*16 ----
        {
            const int c   = t >> 2;
            const int off = (t & 3) * 16;
            const float* src = &K[(size_t)(k0 + c) * KV_DIM + kcol + off];
#pragma unroll
            for (int j = 0; j < 8; ++j) {
                uint32_t hh, ll;
                split_pair(src[2 * j], src[2 * j + 1], hh, ll);
                Kh[c * FSTR + off / 2 + j] = hh;
                Kl[c * FSTR + off / 2 + j] = ll;
            }
        }
        // ---- V tile transposed: Vt[d][j]; 16-bit scattered stores ----
        {
            const int j  = t >> 2;            // kv row 0..63
            const int d0 = (t & 3) * 16;
            const float* src = &V[(size_t)(k0 + j) * KV_DIM + kcol + d0];
            __nv_bfloat16* vh = (__nv_bfloat16*)Vh;
            __nv_bfloat16* vl = (__nv_bfloat16*)Vl;
#pragma unroll
            for (int e = 0; e < 16; ++e) {
                float x = src[e];
                __nv_bfloat16 hb = __float2bfloat16(x);
                float hf = __bfloat162float(hb);
                vh[(d0 + e) * (2 * FSTR) + j] = hb;
                vl[(d0 + e) * (2 * FSTR) + j] = __float2bfloat16(x - hf);
            }
        }
        __syncthreads();

        // ---- S = Q K^T, warp rows = warp*16 .. +16 ----
        float s[8][4];
#pragma unroll
        for (int j = 0; j < 8; ++j)
#pragma unroll
            for (int k = 0; k < 4; ++k) s[j][k] = 0.f;

#pragma unroll
        for (int g = 0; g < 4; ++g) {          // k16 groups over dim 64
            const int aidx = (warp * 16 + r4) * FSTR + g * 8 + c4;
            uint32_t ah[4], al[4];
            ah[0] = Qh[aidx];              al[0] = Ql[aidx];
            ah[1] = Qh[aidx + 8 * FSTR];   al[1] = Ql[aidx + 8 * FSTR];
            ah[2] = Qh[aidx + 4];          al[2] = Ql[aidx + 4];
            ah[3] = Qh[aidx + 8 * FSTR + 4]; al[3] = Ql[aidx + 8 * FSTR + 4];
#pragma unroll
            for (int jn = 0; jn < 8; ++jn) {
                const int bidx = (jn * 8 + r4) * FSTR + g * 8 + c4;
                uint32_t bh[2], bl[2];
                bh[0] = Kh[bidx]; bh[1] = Kh[bidx + 4];
                bl[0] = Kl[bidx]; bl[1] = Kl[bidx + 4];
                mma_bf16(s[jn], al, bh);
                mma_bf16(s[jn], ah, bl);
                mma_bf16(s[jn], ah, bh);
            }
        }

        // ---- online softmax (rows r4 and r4+8 of this warp's 16) ----
        float mx0 = -INFINITY, mx1 = -INFINITY;
#pragma unroll
        for (int jn = 0; jn < 8; ++jn) {
            mx0 = fmaxf(mx0, fmaxf(s[jn][0], s[jn][1]));
            mx1 = fmaxf(mx1, fmaxf(s[jn][2], s[jn][3]));
        }
        mx0 = fmaxf(mx0, __shfl_xor_sync(0xffffffffu, mx0, 1));
        mx0 = fmaxf(mx0, __shfl_xor_sync(0xffffffffu, mx0, 2));
        mx1 = fmaxf(mx1, __shfl_xor_sync(0xffffffffu, mx1, 1));
        mx1 = fmaxf(mx1, __shfl_xor_sync(0xffffffffu, mx1, 2));

        const float mn0 = fmaxf(mrow[0], mx0);
        const float mn1 = fmaxf(mrow[1], mx1);
        const float a0 = __expf(mrow[0] - mn0);
        const float a1 = __expf(mrow[1] - mn1);
        float rs0 = 0.f, rs1 = 0.f;
#pragma unroll
        for (int jn = 0; jn < 8; ++jn) {
            s[jn][0] = __expf(s[jn][0] - mn0); rs0 += s[jn][0];
            s[jn][1] = __expf(s[jn][1] - mn0); rs0 += s[jn][1];
            s[jn][2] = __expf(s[jn][2] - mn1); rs1 += s[jn][2];
            s[jn][3] = __expf(s[jn][3] - mn1); rs1 += s[jn][3];
        }
        rs0 += __shfl_xor_sync(0xffffffffu, rs0, 1);
        rs0 += __shfl_xor_sync(0xffffffffu, rs0, 2);
        rs1 += __shfl_xor_sync(0xffffffffu, rs1, 1);
        rs1 += __shfl_xor_sync(0xffffffffu, rs1, 2);

        lrow[0] = lrow[0] * a0 + rs0;
        lrow[1] = lrow[1] * a1 + rs1;
        mrow[0] = mn0;
        mrow[1] = mn1;
#pragma unroll
        for (int jn = 0; jn < 8; ++jn) {
            o[jn][0] *= a0; o[jn][1] *= a0;
            o[jn][2] *= a1; o[jn][3] *= a1;
        }

        // ---- O += P V : P fragments straight from s accumulators ----
#pragma unroll
        for (int g = 0; g < 4; ++g) {          // kv k16 groups (S ntiles 2g, 2g+1)
            uint32_t ph[4], pl[4];
            {
                float x0 = s[2 * g][0],     x1 = s[2 * g][1];
                float y0 = s[2 * g][2],     y1 = s[2 * g][3];
                float z0 = s[2 * g + 1][0], z1 = s[2 * g + 1][1];
                float w0 = s[2 * g + 1][2], w1 = s[2 * g + 1][3];
                split_pair(x0, x1, ph[0], pl[0]);
                split_pair(y0, y1, ph[1], pl[1]);
                split_pair(z0, z1, ph[2], pl[2]);
                split_pair(w0, w1, ph[3], pl[3]);
            }
#pragma unroll
            for (int jn = 0; jn < 8; ++jn) {   // output-dim ntiles
                const int vidx = (jn * 8 + r4) * FSTR + g * 8 + c4;
                uint32_t bh[2], bl[2];
                bh[0] = Vh[vidx]; bh[1] = Vh[vidx + 4];
                bl[0] = Vl[vidx]; bl[1] = Vl[vidx + 4];
                mma_bf16(o[jn], pl, bh);
                mma_bf16(o[jn], ph, bl);
                mma_bf16(o[jn], ph, bh);
            }
        }
    }

    // ---- normalize + store ----
    const float inv0 = 1.0f / lrow[0];
    const float inv1 = 1.0f / lrow[1];
    const int row0 = s0 + warp * 16 + r4;
#pragma unroll
    for (int jn = 0; jn < 8; ++jn) {
        const int col = qcol + jn * 8 + c4 * 2;
        *(float2*)&O[(size_t)row0 * DM + col] =
            make_float2(o[jn][0] * inv0, o[jn][1] * inv0);
        *(float2*)&O[(size_t)(row0 + 8) * DM + col] =
            make_float2(o[jn][2] * inv1, o[jn][3] * inv1);
    }
}

// ---------------- launch ----------------
extern "C" void kernel_launch(void* const* d_in, const int* in_sizes, int n_in,
                              void* d_out, int out_size)
{
    const float *x, *Wq, *Wk, *Wv, *Wo;
    if (in_sizes[0] == S_LEN * DM) {        // dict order [x, Wq, Wk, Wv, Wo]
        x  = (const float*)d_in[0];
        Wq = (const float*)d_in[1];
        Wk = (const float*)d_in[2];
        Wv = (const float*)d_in[3];
        Wo = (const float*)d_in[4];
    } else {                                 // sorted order [Wk, Wo, Wq, Wv, x]
        Wk = (const float*)d_in[0];
        Wo = (const float*)d_in[1];
        Wq = (const float*)d_in[2];
        Wv = (const float*)d_in[3];
        x  = (const float*)d_in[4];
    }
    float* out = (float*)d_out;

    float *Qp, *Kp, *Vp, *Ap, *rc, *rs;
    cudaGetSymbolAddress((void**)&Qp, g_Q);
    cudaGetSymbolAddress((void**)&Kp, g_K);
    cudaGetSymbolAddress((void**)&Vp, g_V);
    cudaGetSymbolAddress((void**)&Ap, g_A);
    cudaGetSymbolAddress((void**)&rc, g_rc);
    cudaGetSymbolAddress((void**)&rs, g_rs);

    const int gemm_smem = 2 * 4 * 128 * GSTR * sizeof(uint32_t);   // 81920
    const int fa_smem   = (2 * 128 + 4 * 64) * FSTR * sizeof(uint32_t); // 73728
    cudaFuncSetAttribute(gemm_bf16x3, cudaFuncAttributeMaxDynamicSharedMemorySize, gemm_smem);
    cudaFuncSetAttribute(fa_tc, cudaFuncAttributeMaxDynamicSharedMemorySize, fa_smem);

    // 1: rope table (independent — keeps profile slot on heavy kernels)
    rope_table<<<(S_LEN * 32 + 255) / 256, 256>>>(rc, rs);

    // 2-4: projections
    gemm_bf16x3<<<dim3(DM / 128, S_LEN / 128), 256, gemm_smem>>>(x, Wq, Qp, S_LEN, DM, DM);
    gemm_bf16x3<<<dim3(KV_DIM / 128, S_LEN / 128), 256, gemm_smem>>>(x, Wk, Kp, S_LEN, KV_DIM, DM);
    gemm_bf16x3<<<dim3(KV_DIM / 128, S_LEN / 128), 256, gemm_smem>>>(x, Wv, Vp, S_LEN, KV_DIM, DM);

    // 5: rope apply
    rope_apply_qk<<<(S_LEN * 1280 + 255) / 256, 256>>>(Qp, Kp, rc, rs);

    // 6: flash attention (tensor cores)
    fa_tc<<<dim3(S_LEN / 128, NHEADS), 256, fa_smem>>>(Qp, Kp, Vp, Ap);

    // 7: output projection
    gemm_bf16x3<<<dim3(DM / 128, S_LEN / 128), 256, gemm_smem>>>(Ap, Wo, out, S_LEN, DM, DM);
}

// round 6
// speedup vs baseline: 2.7537x; 1.2674x over previous
#include <cuda_runtime.h>
#include <cuda_bf16.h>
#include <math.h>
#include <stdint.h>

#define S_LEN   2048
#define DM      2048
#define KV_DIM  512
#define NHEADS  32
#define NKVH    8
#define HDIM    64

// ---------------- scratch ----------------
__device__ float g_Q[S_LEN * DM];
__device__ float g_K[S_LEN * KV_DIM];
__device__ float g_V[S_LEN * KV_DIM];
__device__ float g_A[S_LEN * DM];
__device__ float g_rc[S_LEN * 32];
__device__ float g_rs[S_LEN * 32];

// ---------------- bf16 helpers ----------------
__device__ __forceinline__ uint32_t pack_bf16x2(float e0, float e1) {
    uint32_t u;
    asm("cvt.rn.bf16x2.f32 %0, %1, %2;" : "=r"(u) : "f"(e1), "f"(e0));
    return u;
}

__device__ __forceinline__ void split_pair(float x0, float x1, uint32_t& h, uint32_t& l) {
    float h0 = __bfloat162float(__float2bfloat16(x0));
    float h1 = __bfloat162float(__float2bfloat16(x1));
    h = pack_bf16x2(h0, h1);
    l = pack_bf16x2(x0 - h0, x1 - h1);
}

__device__ __forceinline__ void mma_bf16(float* c, const uint32_t* a, const uint32_t* b) {
    asm volatile(
        "mma.sync.aligned.m16n8k16.row.col.f32.bf16.bf16.f32 "
        "{%0,%1,%2,%3}, {%4,%5,%6,%7}, {%8,%9}, {%0,%1,%2,%3};"
        : "+f"(c[0]), "+f"(c[1]), "+f"(c[2]), "+f"(c[3])
        : "r"(a[0]), "r"(a[1]), "r"(a[2]), "r"(a[3]), "r"(b[0]), "r"(b[1]));
}

__device__ __forceinline__ void ldsm4(uint32_t* r, uint32_t addr) {
    asm volatile("ldmatrix.sync.aligned.m8n8.x4.shared.b16 {%0,%1,%2,%3}, [%4];"
        : "=r"(r[0]), "=r"(r[1]), "=r"(r[2]), "=r"(r[3]) : "r"(addr));
}

// ---------------- bf16x3 GEMM with optional fused second B/C ----------------
// C[M, N0(+N1)] = A[M,K] @ [B0;B1][N,K]^T.  BM=BN=128, BK=16.
// 256 threads (8 warps: 4m x 2n), warp tile 32x64, 2 CTAs/SM.
#define GBK  16
#define GSTR 12   // uints per smem row (8 data + 4 pad) -> ldmatrix conflict-free

__global__ __launch_bounds__(256, 2) void gemm_bf16x3(
    const float* __restrict__ A, const float* __restrict__ B0,
    const float* __restrict__ B1, float* __restrict__ C0, float* __restrict__ C1,
    int M, int N0, int N1, int K)
{
    extern __shared__ uint32_t gsm[];
    const int TILE = 128 * GSTR;   // 1536 uints per sub-tile

    const int t    = threadIdx.x;
    const int lane = t & 31;
    const int warp = t >> 5;
    const int wm   = warp >> 1;
    const int wn   = warp & 1;
    const int m0   = blockIdx.y * 128;
    const int nblk = blockIdx.x * 128;

    // select B/C half (fused KV support)
    const float* Bp;
    float* Cp;
    int ldc, nc0;
    if (nblk < N0) { Bp = B0 + (size_t)nblk * K;        Cp = C0; ldc = N0; nc0 = nblk; }
    else           { Bp = B1 + (size_t)(nblk - N0) * K; Cp = C1; ldc = N1; nc0 = nblk - N0; }

    const int lrow = t >> 1;          // 0..127
    const int lco  = (t & 1) * 8;     // float col base: 0 or 8

    // ldmatrix per-lane offsets (uints within tile)
    const int aRow = wm * 32 + (lane & 15);
    const int aK   = (lane >> 4) * 4;
    const int bRow = wn * 64 + (lane & 7) + ((lane & 16) >> 1);
    const int bK   = (lane & 8) ? 4 : 0;

    uint32_t smBase = (uint32_t)__cvta_generic_to_shared(gsm);
    // byte offsets of the four sub-tiles within a buffer
    const uint32_t aHiOff = 0, aLoOff = TILE * 4, bHiOff = 2 * TILE * 4, bLoOff = 3 * TILE * 4;
    const uint32_t bufStride = 4 * TILE * 4;   // bytes per buffer

    const uint32_t aAddr = (uint32_t)(aRow * GSTR + aK) * 4;
    const uint32_t bAddr = (uint32_t)(bRow * GSTR + bK) * 4;

    float acc[2][8][4];
#pragma unroll
    for (int i = 0; i < 2; ++i)
#pragma unroll
        for (int j = 0; j < 8; ++j)
#pragma unroll
            for (int k = 0; k < 4; ++k) acc[i][j][k] = 0.f;

    float4 pa[2], pb[2];

    // prologue: tile 0
#pragma unroll
    for (int i = 0; i < 2; ++i) {
        pa[i] = *(const float4*)&A[(size_t)(m0 + lrow) * K + lco + i * 4];
        pb[i] = *(const float4*)&Bp[(size_t)lrow * K + lco + i * 4];
    }
    {
        uint32_t* aHi = gsm;              uint32_t* aLo = gsm + TILE;
        uint32_t* bHi = gsm + 2 * TILE;   uint32_t* bLo = gsm + 3 * TILE;
        const float* fa = (const float*)pa;
        const float* fb = (const float*)pb;
#pragma unroll
        for (int j = 0; j < 4; ++j) {
            uint32_t h, l;
            split_pair(fa[2 * j], fa[2 * j + 1], h, l);
            aHi[lrow * GSTR + lco / 2 + j] = h;
            aLo[lrow * GSTR + lco / 2 + j] = l;
            split_pair(fb[2 * j], fb[2 * j + 1], h, l);
            bHi[lrow * GSTR + lco / 2 + j] = h;
            bLo[lrow * GSTR + lco / 2 + j] = l;
        }
    }
    __syncthreads();

    const int nt = K / GBK;
    for (int tt = 0; tt < nt; ++tt) {
        const uint32_t bb = smBase + (uint32_t)(tt & 1) * bufStride;

        if (tt + 1 < nt) {
            const int k0 = (tt + 1) * GBK;
#pragma unroll
            for (int i = 0; i < 2; ++i) {
                pa[i] = *(const float4*)&A[(size_t)(m0 + lrow) * K + k0 + lco + i * 4];
                pb[i] = *(const float4*)&Bp[(size_t)lrow * K + k0 + lco + i * 4];
            }
        }

        // A fragments for this k16 group
        uint32_t ah[2][4], al[2][4];
#pragma unroll
        for (int im = 0; im < 2; ++im) {
            const uint32_t ro = (uint32_t)(im * 16 * GSTR) * 4;
            ldsm4(ah[im], bb + aHiOff + aAddr + ro);
            ldsm4(al[im], bb + aLoOff + aAddr + ro);
        }

#pragma unroll
        for (int jj = 0; jj < 4; ++jj) {   // pairs of n8 tiles
            uint32_t bh[4], bl[4];
            const uint32_t ro = (uint32_t)(jj * 16 * GSTR) * 4;
            ldsm4(bh, bb + bHiOff + bAddr + ro);
            ldsm4(bl, bb + bLoOff + bAddr + ro);
#pragma unroll
            for (int hf = 0; hf < 2; ++hf) {
                const int ntile = jj * 2 + hf;
#pragma unroll
                for (int im = 0; im < 2; ++im) {
                    mma_bf16(acc[im][ntile], al[im], bh + hf * 2);
                    mma_bf16(acc[im][ntile], ah[im], bl + hf * 2);
                    mma_bf16(acc[im][ntile], ah[im], bh + hf * 2);
                }
            }
        }

        if (tt + 1 < nt) {
            uint32_t* nb = gsm + ((tt + 1) & 1) * 4 * TILE;
            uint32_t* aHi = nb;              uint32_t* aLo = nb + TILE;
            uint32_t* bHi = nb + 2 * TILE;   uint32_t* bLo = nb + 3 * TILE;
            const float* fa = (const float*)pa;
            const float* fb = (const float*)pb;
#pragma unroll
            for (int j = 0; j < 4; ++j) {
                uint32_t h, l;
                split_pair(fa[2 * j], fa[2 * j + 1], h, l);
                aHi[lrow * GSTR + lco / 2 + j] = h;
                aLo[lrow * GSTR + lco / 2 + j] = l;
                split_pair(fb[2 * j], fb[2 * j + 1], h, l);
                bHi[lrow * GSTR + lco / 2 + j] = h;
                bLo[lrow * GSTR + lco / 2 + j] = l;
            }
            __syncthreads();
        }
    }

    // epilogue
    const int r4 = lane >> 2;
    const int c4 = lane & 3;
    const int crow0 = m0 + wm * 32 + r4;
    const int ccol0 = nc0 + wn * 64 + c4 * 2;
#pragma unroll
    for (int im = 0; im < 2; ++im) {
#pragma unroll
        for (int jn = 0; jn < 8; ++jn) {
            const int row = crow0 + im * 16;
            const int col = ccol0 + jn * 8;
            *(float2*)&Cp[(size_t)row * ldc + col] =
                make_float2(acc[im][jn][0], acc[im][jn][1]);
            *(float2*)&Cp[(size_t)(row + 8) * ldc + col] =
                make_float2(acc[im][jn][2], acc[im][jn][3]);
        }
    }
}

// ---------------- RoPE ----------------
__global__ void rope_table(float* __restrict__ rc, float* __restrict__ rs)
{
    int idx = blockIdx.x * blockDim.x + threadIdx.x;
    if (idx >= S_LEN * 32) return;
    int s = idx >> 5;
    int i = idx & 31;
    double ang = (double)s * pow(10000.0, -(double)i / 32.0);
    double sd, cd;
    sincos(ang, &sd, &cd);
    rc[idx] = (float)cd;
    rs[idx] = (float)sd;
}

__global__ void rope_apply_qk(float* __restrict__ Q, float* __restrict__ K,
                              const float* __restrict__ rc, const float* __restrict__ rs)
{
    int idx = blockIdx.x * blockDim.x + threadIdx.x;
    const int per_row = 1280;
    if (idx >= S_LEN * per_row) return;
    int s = idx / per_row;
    int r = idx - s * per_row;

    float* X;
    int ncols, rr;
    if (r < 1024) { X = Q; ncols = DM;     rr = r; }
    else          { X = K; ncols = KV_DIM; rr = r - 1024; }
    int head = rr >> 5;
    int i    = rr & 31;

    float c  = rc[(s << 5) + i];
    float sn = rs[(s << 5) + i];

    size_t base = (size_t)s * ncols + head * 64 + i;
    float x1 = X[base];
    float x2 = X[base + 32];
    X[base]      = x1 * c - x2 * sn;
    X[base + 32] = x2 * c + x1 * sn;
}

// ---------------- Flash attention, tensor-core bf16x3 + ldmatrix ----------------
#define FSTR 36

__global__ __launch_bounds__(256) void fa_tc(
    const float* __restrict__ Q, const float* __restrict__ K,
    const float* __restrict__ V, float* __restrict__ O)
{
    extern __shared__ uint32_t fsm[];
    uint32_t* Qh = fsm;                       // 128*FSTR
    uint32_t* Ql = Qh + 128 * FSTR;
    uint32_t* Kh = Ql + 128 * FSTR;           // 64*FSTR
    uint32_t* Kl = Kh + 64 * FSTR;
    uint32_t* Vh = Kl + 64 * FSTR;            // V^T: [d][j]
    uint32_t* Vl = Vh + 64 * FSTR;

    const int t    = threadIdx.x;
    const int lane = t & 31;
    const int warp = t >> 5;
    const int r4   = lane >> 2;
    const int c4   = lane & 3;
    const int qb   = blockIdx.x;
    const int h    = blockIdx.y;
    const int s0   = qb * 128;
    const int kvh  = h / (NHEADS / NKVH);
    const int qcol = h * HDIM;
    const int kcol = kvh * HDIM;
    const float scale = 0.125f;

    uint32_t smBase = (uint32_t)__cvta_generic_to_shared(fsm);
    const uint32_t QhO = 0, QlO = 128u * FSTR * 4;
    const uint32_t KhO = QlO + 128u * FSTR * 4, KlO = KhO + 64u * FSTR * 4;
    const uint32_t VhO = KlO + 64u * FSTR * 4,  VlO = VhO + 64u * FSTR * 4;

    // ldmatrix lane offsets
    const uint32_t aAddr = (uint32_t)((warp * 16 + (lane & 15)) * FSTR + (lane >> 4) * 4) * 4;
    const int bRow = (lane & 7) + ((lane & 16) >> 1);
    const uint32_t bAddr = (uint32_t)(bRow * FSTR + ((lane & 8) ? 4 : 0)) * 4;

    // ---- load Q tile (scaled) ----
    {
        const int row  = t >> 1;
        const int half = (t & 1) * 32;
        const float* src = &Q[(size_t)(s0 + row) * DM + qcol + half];
#pragma unroll
        for (int j = 0; j < 16; ++j) {
            float x0 = src[2 * j]     * scale;
            float x1 = src[2 * j + 1] * scale;
            uint32_t hh, ll;
            split_pair(x0, x1, hh, ll);
            Qh[row * FSTR + half / 2 + j] = hh;
            Ql[row * FSTR + half / 2 + j] = ll;
        }
    }

    float o[8][4];
#pragma unroll
    for (int j = 0; j < 8; ++j)
#pragma unroll
        for (int k = 0; k < 4; ++k) o[j][k] = 0.f;
    float mrow[2] = {-INFINITY, -INFINITY};
    float lrow[2] = {0.f, 0.f};

    for (int k0 = 0; k0 < S_LEN; k0 += 64) {
        __syncthreads();

        // ---- K tile ----
        {
            const int c   = t >> 2;
            const int off = (t & 3) * 16;
            const float* src = &K[(size_t)(k0 + c) * KV_DIM + kcol + off];
#pragma unroll
            for (int j = 0; j < 8; ++j) {
                uint32_t hh, ll;
                split_pair(src[2 * j], src[2 * j + 1], hh, ll);
                Kh[c * FSTR + off / 2 + j] = hh;
                Kl[c * FSTR + off / 2 + j] = ll;
            }
        }
        // ---- V tile transposed ----
        {
            const int j  = t >> 2;
            const int d0 = (t & 3) * 16;
            const float* src = &V[(size_t)(k0 + j) * KV_DIM + kcol + d0];
            __nv_bfloat16* vh = (__nv_bfloat16*)Vh;
            __nv_bfloat16* vl = (__nv_bfloat16*)Vl;
#pragma unroll
            for (int e = 0; e < 16; ++e) {
                float x = src[e];
                __nv_bfloat16 hb = __float2bfloat16(x);
                float hf = __bfloat162float(hb);
                vh[(d0 + e) * (2 * FSTR) + j] = hb;
                vl[(d0 + e) * (2 * FSTR) + j] = __float2bfloat16(x - hf);
            }
        }
        __syncthreads();

        // ---- S = Q K^T ----
        float s[8][4];
#pragma unroll
        for (int j = 0; j < 8; ++j)
#pragma unroll
            for (int k = 0; k < 4; ++k) s[j][k] = 0.f;

#pragma unroll
        for (int g = 0; g < 4; ++g) {
            const uint32_t gB = (uint32_t)(g * 8) * 4;
            uint32_t ah[4], al[4];
            ldsm4(ah, smBase + QhO + aAddr + gB);
            ldsm4(al, smBase + QlO + aAddr + gB);
#pragma unroll
            for (int jj = 0; jj < 4; ++jj) {
                const uint32_t ro = (uint32_t)(jj * 16 * FSTR) * 4;
                uint32_t bh[4], bl[4];
                ldsm4(bh, smBase + KhO + bAddr + ro + gB);
                ldsm4(bl, smBase + KlO + bAddr + ro + gB);
#pragma unroll
                for (int hf = 0; hf < 2; ++hf) {
                    mma_bf16(s[jj * 2 + hf], al, bh + hf * 2);
                    mma_bf16(s[jj * 2 + hf], ah, bl + hf * 2);
                    mma_bf16(s[jj * 2 + hf], ah, bh + hf * 2);
                }
            }
        }

        // ---- online softmax ----
        float mx0 = -INFINITY, mx1 = -INFINITY;
#pragma unroll
        for (int jn = 0; jn < 8; ++jn) {
            mx0 = fmaxf(mx0, fmaxf(s[jn][0], s[jn][1]));
            mx1 = fmaxf(mx1, fmaxf(s[jn][2], s[jn][3]));
        }
        mx0 = fmaxf(mx0, __shfl_xor_sync(0xffffffffu, mx0, 1));
        mx0 = fmaxf(mx0, __shfl_xor_sync(0xffffffffu, mx0, 2));
        mx1 = fmaxf(mx1, __shfl_xor_sync(0xffffffffu, mx1, 1));
        mx1 = fmaxf(mx1, __shfl_xor_sync(0xffffffffu, mx1, 2));

        const float mn0 = fmaxf(mrow[0], mx0);
        const float mn1 = fmaxf(mrow[1], mx1);
        const float a0 = __expf(mrow[0] - mn0);
        const float a1 = __expf(mrow[1] - mn1);
        float rs0 = 0.f, rs1 = 0.f;
#pragma unroll
        for (int jn = 0; jn < 8; ++jn) {
            s[jn][0] = __expf(s[jn][0] - mn0); rs0 += s[jn][0];
            s[jn][1] = __expf(s[jn][1] - mn0); rs0 += s[jn][1];
            s[jn][2] = __expf(s[jn][2] - mn1); rs1 += s[jn][2];
            s[jn][3] = __expf(s[jn][3] - mn1); rs1 += s[jn][3];
        }
        rs0 += __shfl_xor_sync(0xffffffffu, rs0, 1);
        rs0 += __shfl_xor_sync(0xffffffffu, rs0, 2);
        rs1 += __shfl_xor_sync(0xffffffffu, rs1, 1);
        rs1 += __shfl_xor_sync(0xffffffffu, rs1, 2);

        lrow[0] = lrow[0] * a0 + rs0;
        lrow[1] = lrow[1] * a1 + rs1;
        mrow[0] = mn0;
        mrow[1] = mn1;
#pragma unroll
        for (int jn = 0; jn < 8; ++jn) {
            o[jn][0] *= a0; o[jn][1] *= a0;
            o[jn][2] *= a1; o[jn][3] *= a1;
        }

        // ---- O += P V ----
#pragma unroll
        for (int g = 0; g < 4; ++g) {
            uint32_t ph[4], pl[4];
            split_pair(s[2 * g][0],     s[2 * g][1],     ph[0], pl[0]);
            split_pair(s[2 * g][2],     s[2 * g][3],     ph[1], pl[1]);
            split_pair(s[2 * g + 1][0], s[2 * g + 1][1], ph[2], pl[2]);
            split_pair(s[2 * g + 1][2], s[2 * g + 1][3], ph[3], pl[3]);
            const uint32_t gB = (uint32_t)(g * 8) * 4;
#pragma unroll
            for (int jj = 0; jj < 4; ++jj) {
                const uint32_t ro = (uint32_t)(jj * 16 * FSTR) * 4;
                uint32_t vh[4], vl[4];
                ldsm4(vh, smBase + VhO + bAddr + ro + gB);
                ldsm4(vl, smBase + VlO + bAddr + ro + gB);
#pragma unroll
                for (int hf = 0; hf < 2; ++hf) {
                    mma_bf16(o[jj * 2 + hf], pl, vh + hf * 2);
                    mma_bf16(o[jj * 2 + hf], ph, vl + hf * 2);
                    mma_bf16(o[jj * 2 + hf], ph, vh + hf * 2);
                }
            }
        }
    }

    // ---- normalize + store ----
    const float inv0 = 1.0f / lrow[0];
    const float inv1 = 1.0f / lrow[1];
    const int row0 = s0 + warp * 16 + r4;
#pragma unroll
    for (int jn = 0; jn < 8; ++jn) {
        const int col = qcol + jn * 8 + c4 * 2;
        *(float2*)&O[(size_t)row0 * DM + col] =
            make_float2(o[jn][0] * inv0, o[jn][1] * inv0);
        *(float2*)&O[(size_t)(row0 + 8) * DM + col] =
            make_float2(o[jn][2] * inv1, o[jn][3] * inv1);
    }
}

// ---------------- launch ----------------
extern "C" void kernel_launch(void* const* d_in, const int* in_sizes, int n_in,
                              void* d_out, int out_size)
{
    const float *x, *Wq, *Wk, *Wv, *Wo;
    if (in_sizes[0] == S_LEN * DM) {        // dict order [x, Wq, Wk, Wv, Wo]
        x  = (const float*)d_in[0];
        Wq = (const float*)d_in[1];
        Wk = (const float*)d_in[2];
        Wv = (const float*)d_in[3];
        Wo = (const float*)d_in[4];
    } else {                                 // sorted order [Wk, Wo, Wq, Wv, x]
        Wk = (const float*)d_in[0];
        Wo = (const float*)d_in[1];
        Wq = (const float*)d_in[2];
        Wv = (const float*)d_in[3];
        x  = (const float*)d_in[4];
    }
    float* out = (float*)d_out;

    float *Qp, *Kp, *Vp, *Ap, *rc, *rs;
    cudaGetSymbolAddress((void**)&Qp, g_Q);
    cudaGetSymbolAddress((void**)&Kp, g_K);
    cudaGetSymbolAddress((void**)&Vp, g_V);
    cudaGetSymbolAddress((void**)&Ap, g_A);
    cudaGetSymbolAddress((void**)&rc, g_rc);
    cudaGetSymbolAddress((void**)&rs, g_rs);

    const int gemm_smem = 2 * 4 * 128 * GSTR * sizeof(uint32_t);        // 49152
    const int fa_smem   = (2 * 128 + 4 * 64) * FSTR * sizeof(uint32_t); // 73728
    cudaFuncSetAttribute(gemm_bf16x3, cudaFuncAttributeMaxDynamicSharedMemorySize, gemm_smem);
    cudaFuncSetAttribute(fa_tc, cudaFuncAttributeMaxDynamicSharedMemorySize, fa_smem);

    // 1: rope table
    rope_table<<<(S_LEN * 32 + 255) / 256, 256>>>(rc, rs);

    // 2: Q projection
    gemm_bf16x3<<<dim3(DM / 128, S_LEN / 128), 256, gemm_smem>>>(
        x, Wq, (const float*)nullptr, Qp, (float*)nullptr, S_LEN, DM, 0, DM);

    // 3: fused K+V projection (one wave of 128 CTAs)
    gemm_bf16x3<<<dim3(2 * KV_DIM / 128, S_LEN / 128), 256, gemm_smem>>>(
        x, Wk, Wv, Kp, Vp, S_LEN, KV_DIM, KV_DIM, DM);

    // 4: rope apply
    rope_apply_qk<<<(S_LEN * 1280 + 255) / 256, 256>>>(Qp, Kp, rc, rs);

    // 5: flash attention
    fa_tc<<<dim3(S_LEN / 128, NHEADS), 256, fa_smem>>>(Qp, Kp, Vp, Ap);

    // 6: output projection (profiled launch under -s 5 -c 1)
    gemm_bf16x3<<<dim3(DM / 128, S_LEN / 128), 256, gemm_smem>>>(
        Ap, Wo, (const float*)nullptr, out, (float*)nullptr, S_LEN, DM, 0, DM);
}

// round 7
// speedup vs baseline: 3.4803x; 1.2638x over previous
#include <cuda_runtime.h>
#include <cuda_bf16.h>
#include <math.h>
#include <stdint.h>

#define S_LEN   2048
#define DM      2048
#define KV_DIM  512
#define NHEADS  32
#define NKVH    8
#define HDIM    64
#define QKV_N   3072

// ---------------- bf16 hi/lo planes (allocation-free scratch) ----------------
__device__ __nv_bfloat16 g_xh[S_LEN * DM],     g_xl[S_LEN * DM];
__device__ __nv_bfloat16 g_wh[QKV_N * DM],     g_wl[QKV_N * DM];     // Wq|Wk|Wv rows
__device__ __nv_bfloat16 g_woh[DM * DM],       g_wol[DM * DM];
__device__ __nv_bfloat16 g_qkvh[S_LEN * QKV_N], g_qkvl[S_LEN * QKV_N];
__device__ __nv_bfloat16 g_qh[S_LEN * DM],     g_ql[S_LEN * DM];     // roped+scaled
__device__ __nv_bfloat16 g_kh[S_LEN * KV_DIM], g_kl[S_LEN * KV_DIM]; // roped
__device__ __nv_bfloat16 g_vth[KV_DIM * S_LEN], g_vtl[KV_DIM * S_LEN]; // V^T [c][s]
__device__ __nv_bfloat16 g_ah[S_LEN * DM],     g_al[S_LEN * DM];     // attn out
__device__ float g_rc[S_LEN * 32], g_rs[S_LEN * 32];

// ---------------- helpers ----------------
__device__ __forceinline__ uint32_t pack_bf16x2(float e0, float e1) {
    uint32_t u;
    asm("cvt.rn.bf16x2.f32 %0, %1, %2;" : "=r"(u) : "f"(e1), "f"(e0));
    return u;
}
__device__ __forceinline__ void split_pair(float x0, float x1, uint32_t& h, uint32_t& l) {
    float h0 = __bfloat162float(__float2bfloat16(x0));
    float h1 = __bfloat162float(__float2bfloat16(x1));
    h = pack_bf16x2(h0, h1);
    l = pack_bf16x2(x0 - h0, x1 - h1);
}
__device__ __forceinline__ void mma_bf16(float* c, const uint32_t* a, const uint32_t* b) {
    asm volatile(
        "mma.sync.aligned.m16n8k16.row.col.f32.bf16.bf16.f32 "
        "{%0,%1,%2,%3}, {%4,%5,%6,%7}, {%8,%9}, {%0,%1,%2,%3};"
        : "+f"(c[0]), "+f"(c[1]), "+f"(c[2]), "+f"(c[3])
        : "r"(a[0]), "r"(a[1]), "r"(a[2]), "r"(a[3]), "r"(b[0]), "r"(b[1]));
}
__device__ __forceinline__ void ldsm4(uint32_t* r, uint32_t addr) {
    asm volatile("ldmatrix.sync.aligned.m8n8.x4.shared.b16 {%0,%1,%2,%3}, [%4];"
        : "=r"(r[0]), "=r"(r[1]), "=r"(r[2]), "=r"(r[3]) : "r"(addr));
}
__device__ __forceinline__ void cpa16(uint32_t dst, const void* src) {
    asm volatile("cp.async.cg.shared.global [%0], [%1], 16;" :: "r"(dst), "l"(src));
}
__device__ __forceinline__ void cp_commit() { asm volatile("cp.async.commit_group;"); }
__device__ __forceinline__ void cp_wait0()  { asm volatile("cp.async.wait_group 0;"); }
__device__ __forceinline__ void cp_wait1()  { asm volatile("cp.async.wait_group 1;"); }

// ---------------- input conversion: f32 -> bf16 hi/lo planes ----------------
// segments (in float4 quads): x | Wq | Wk | Wv | Wo
#define QX   (S_LEN * DM / 4)
#define QWQ  (DM * DM / 4)
#define QWK  (KV_DIM * DM / 4)
#define QWV  (KV_DIM * DM / 4)
#define QWO  (DM * DM / 4)
#define QTOT (QX + QWQ + QWK + QWV + QWO)

__global__ void conv_all(const float* __restrict__ x,  const float* __restrict__ wq,
                         const float* __restrict__ wk, const float* __restrict__ wv,
                         const float* __restrict__ wo)
{
    int q = blockIdx.x * blockDim.x + threadIdx.x;
    if (q >= QTOT) return;
    const float* src;
    __nv_bfloat16 *dh, *dl;
    int lq;
    if (q < QX)                       { src = x;  dh = g_xh;  dl = g_xl;  lq = q; }
    else if (q < QX + QWQ)            { src = wq; dh = g_wh;  dl = g_wl;  lq = q - QX; }
    else if (q < QX + QWQ + QWK)      { src = wk; dh = g_wh + DM * DM;  dl = g_wl + DM * DM;  lq = q - QX - QWQ; }
    else if (q < QX + QWQ + QWK + QWV){ src = wv; dh = g_wh + DM * DM + KV_DIM * DM; dl = g_wl + DM * DM + KV_DIM * DM; lq = q - QX - QWQ - QWK; }
    else                              { src = wo; dh = g_woh; dl = g_wol; lq = q - QX - QWQ - QWK - QWV; }

    float4 v = ((const float4*)src)[lq];
    uint32_t h0, l0, h1, l1;
    split_pair(v.x, v.y, h0, l0);
    split_pair(v.z, v.w, h1, l1);
    uint32_t* dh32 = (uint32_t*)dh;
    uint32_t* dl32 = (uint32_t*)dl;
    dh32[lq * 2] = h0; dh32[lq * 2 + 1] = h1;
    dl32[lq * 2] = l0; dl32[lq * 2 + 1] = l1;
}

// ---------------- bf16-plane GEMM: C[M,N] = A[M,K] @ B[N,K]^T ----------------
// BM=BN=128, BK=16, 256 threads (8 warps: 4m x 2n), 2-stage cp.async, 2 CTAs/SM.
#define GSTR 12                 // uints per smem row (8 data + 4 pad)
#define GTILE (128 * GSTR)      // uints per sub-tile

__global__ __launch_bounds__(256, 2) void gemm_planes(
    const __nv_bfloat16* __restrict__ Ah, const __nv_bfloat16* __restrict__ Al,
    const __nv_bfloat16* __restrict__ Bh, const __nv_bfloat16* __restrict__ Bl,
    float* __restrict__ Cf, __nv_bfloat16* __restrict__ Ch, __nv_bfloat16* __restrict__ Cl,
    int M, int N, int K)
{
    extern __shared__ uint32_t gsm[];

    const int t    = threadIdx.x;
    const int lane = t & 31;
    const int warp = t >> 5;
    const int wm   = warp >> 1;
    const int wn   = warp & 1;
    const int m0   = blockIdx.y * 128;
    const int n0   = blockIdx.x * 128;

    const int lrow = t >> 1;         // 0..127
    const int lhalf = t & 1;         // 16B chunk select (8 bf16)

    uint32_t smBase = (uint32_t)__cvta_generic_to_shared(gsm);
    const uint32_t bufStride = 4u * GTILE * 4;   // bytes per stage
    const uint32_t aHiB = 0, aLoB = GTILE * 4, bHiB = 2u * GTILE * 4, bLoB = 3u * GTILE * 4;

    const uint32_t ldDst = (uint32_t)(lrow * GSTR + lhalf * 4) * 4;  // bytes in tile

    const uint32_t aAddr = (uint32_t)((wm * 32 + (lane & 15)) * GSTR + (lane >> 4) * 4) * 4;
    const int bRow = wn * 64 + (lane & 7) + ((lane & 16) >> 1);
    const uint32_t bAddr = (uint32_t)(bRow * GSTR + ((lane & 8) ? 4 : 0)) * 4;

    const __nv_bfloat16* aSrcH = Ah + (size_t)(m0 + lrow) * K + lhalf * 8;
    const __nv_bfloat16* aSrcL = Al + (size_t)(m0 + lrow) * K + lhalf * 8;
    const __nv_bfloat16* bSrcH = Bh + (size_t)(n0 + lrow) * K + lhalf * 8;
    const __nv_bfloat16* bSrcL = Bl + (size_t)(n0 + lrow) * K + lhalf * 8;

    float acc[2][8][4];
#pragma unroll
    for (int i = 0; i < 2; ++i)
#pragma unroll
        for (int j = 0; j < 8; ++j)
#pragma unroll
            for (int k = 0; k < 4; ++k) acc[i][j][k] = 0.f;

    const int nt = K / 16;

    // prologue: stage 0
    {
        uint32_t d = smBase + ldDst;
        cpa16(d + aHiB, aSrcH);
        cpa16(d + aLoB, aSrcL);
        cpa16(d + bHiB, bSrcH);
        cpa16(d + bLoB, bSrcL);
        cp_commit();
    }

    for (int tt = 0; tt < nt; ++tt) {
        if (tt + 1 < nt) {
            const int k0 = (tt + 1) * 16;
            uint32_t d = smBase + (uint32_t)((tt + 1) & 1) * bufStride + ldDst;
            cpa16(d + aHiB, aSrcH + k0);
            cpa16(d + aLoB, aSrcL + k0);
            cpa16(d + bHiB, bSrcH + k0);
            cpa16(d + bLoB, bSrcL + k0);
            cp_commit();
            cp_wait1();
        } else {
            cp_wait0();
        }
        __syncthreads();

        const uint32_t bb = smBase + (uint32_t)(tt & 1) * bufStride;

        uint32_t ah[2][4], al[2][4];
#pragma unroll
        for (int im = 0; im < 2; ++im) {
            const uint32_t ro = (uint32_t)(im * 16 * GSTR) * 4;
            ldsm4(ah[im], bb + aHiB + aAddr + ro);
            ldsm4(al[im], bb + aLoB + aAddr + ro);
        }
#pragma unroll
        for (int jj = 0; jj < 4; ++jj) {
            uint32_t bh[4], bl[4];
            const uint32_t ro = (uint32_t)(jj * 16 * GSTR) * 4;
            ldsm4(bh, bb + bHiB + bAddr + ro);
            ldsm4(bl, bb + bLoB + bAddr + ro);
#pragma unroll
            for (int hf = 0; hf < 2; ++hf) {
                const int ntile = jj * 2 + hf;
#pragma unroll
                for (int im = 0; im < 2; ++im) {
                    mma_bf16(acc[im][ntile], al[im], bh + hf * 2);
                    mma_bf16(acc[im][ntile], ah[im], bl + hf * 2);
                    mma_bf16(acc[im][ntile], ah[im], bh + hf * 2);
                }
            }
        }
        __syncthreads();   // compute done before this buffer is refilled
    }

    // epilogue
    const int r4 = lane >> 2;
    const int c4 = lane & 3;
    const int crow0 = m0 + wm * 32 + r4;
    const int ccol0 = n0 + wn * 64 + c4 * 2;
#pragma unroll
    for (int im = 0; im < 2; ++im) {
#pragma unroll
        for (int jn = 0; jn < 8; ++jn) {
            const int row = crow0 + im * 16;
            const int col = ccol0 + jn * 8;
            float v0 = acc[im][jn][0], v1 = acc[im][jn][1];
            float v2 = acc[im][jn][2], v3 = acc[im][jn][3];
            if (Cf) {
                *(float2*)&Cf[(size_t)row * N + col]       = make_float2(v0, v1);
                *(float2*)&Cf[(size_t)(row + 8) * N + col] = make_float2(v2, v3);
            } else {
                uint32_t h, l;
                split_pair(v0, v1, h, l);
                *(uint32_t*)&Ch[(size_t)row * N + col] = h;
                *(uint32_t*)&Cl[(size_t)row * N + col] = l;
                split_pair(v2, v3, h, l);
                *(uint32_t*)&Ch[(size_t)(row + 8) * N + col] = h;
                *(uint32_t*)&Cl[(size_t)(row + 8) * N + col] = l;
            }
        }
    }
}

// ---------------- RoPE table ----------------
__global__ void rope_table(float* __restrict__ rc, float* __restrict__ rs)
{
    int idx = blockIdx.x * blockDim.x + threadIdx.x;
    if (idx >= S_LEN * 32) return;
    int s = idx >> 5;
    int i = idx & 31;
    double ang = (double)s * pow(10000.0, -(double)i / 32.0);
    double sd, cd;
    sincos(ang, &sd, &cd);
    rc[idx] = (float)cd;
    rs[idx] = (float)sd;
}

// ---------------- RoPE + scale on QKV planes -> Q/K planes ----------------
__global__ void rope_qk_planes(const float* __restrict__ rc, const float* __restrict__ rs)
{
    int idx = blockIdx.x * blockDim.x + threadIdx.x;
    const int per_row = 1280;   // 1024 Q pairs + 256 K pairs
    if (idx >= S_LEN * per_row) return;
    int s = idx / per_row;
    int r = idx - s * per_row;

    int srcCol, dstCol, i;
    __nv_bfloat16 *dh, *dl;
    float sc;
    if (r < 1024) {        // Q
        int head = r >> 5; i = r & 31;
        srcCol = head * 64 + i;
        dstCol = srcCol;
        dh = g_qh; dl = g_ql;
        sc = 0.125f;
    } else {               // K
        int rr = r - 1024;
        int kvh = rr >> 5; i = rr & 31;
        srcCol = 2048 + kvh * 64 + i;
        dstCol = kvh * 64 + i;
        dh = g_kh; dl = g_kl;
        sc = 1.0f;
    }
    const int ldDst = (r < 1024) ? DM : KV_DIM;

    float c  = rc[(s << 5) + i];
    float sn = rs[(s << 5) + i];

    size_t b1 = (size_t)s * QKV_N + srcCol;
    float x1 = __bfloat162float(g_qkvh[b1])      + __bfloat162float(g_qkvl[b1]);
    float x2 = __bfloat162float(g_qkvh[b1 + 32]) + __bfloat162float(g_qkvl[b1 + 32]);

    float y1 = (x1 * c - x2 * sn) * sc;
    float y2 = (x2 * c + x1 * sn) * sc;

    size_t d1 = (size_t)s * ldDst + dstCol;
    __nv_bfloat16 h1 = __float2bfloat16(y1);
    __nv_bfloat16 h2 = __float2bfloat16(y2);
    dh[d1]      = h1;  dl[d1]      = __float2bfloat16(y1 - __bfloat162float(h1));
    dh[d1 + 32] = h2;  dl[d1 + 32] = __float2bfloat16(y2 - __bfloat162float(h2));
}

// ---------------- V transpose: QKV planes cols [2560,3072) -> Vt[c][s] ----------------
__global__ void vt_transpose()
{
    __shared__ __nv_bfloat16 th[32][33], tl[32][33];
    const int tx = threadIdx.x, ty = threadIdx.y;   // (32, 8)
    const int s0 = blockIdx.x * 32;
    const int c0 = blockIdx.y * 32;
#pragma unroll
    for (int k = 0; k < 4; ++k) {
        int s = s0 + ty + k * 8;
        th[ty + k * 8][tx] = g_qkvh[(size_t)s * QKV_N + 2560 + c0 + tx];
        tl[ty + k * 8][tx] = g_qkvl[(size_t)s * QKV_N + 2560 + c0 + tx];
    }
    __syncthreads();
#pragma unroll
    for (int k = 0; k < 4; ++k) {
        int c = c0 + ty + k * 8;
        g_vth[(size_t)c * S_LEN + s0 + tx] = th[tx][ty + k * 8];
        g_vtl[(size_t)c * S_LEN + s0 + tx] = tl[tx][ty + k * 8];
    }
}

// ---------------- Flash attention: bf16x3 planes + cp.async double buffer ----------------
#define FSTR 36   // uints per smem row (32 data + 4 pad)

__global__ __launch_bounds__(256) void fa_tc()
{
    extern __shared__ uint32_t fsm[];

    const int t    = threadIdx.x;
    const int lane = t & 31;
    const int warp = t >> 5;
    const int r4   = lane >> 2;
    const int c4   = lane & 3;
    const int s0   = blockIdx.x * 128;
    const int h    = blockIdx.y;
    const int kvh  = h / (NHEADS / NKVH);
    const int qcol = h * HDIM;
    const int kcol = kvh * HDIM;

    uint32_t smBase = (uint32_t)__cvta_generic_to_shared(fsm);
    const uint32_t QhB = 0, QlB = 128u * FSTR * 4;
    const uint32_t kvBase = 2u * 128u * FSTR * 4;          // 36864
    const uint32_t kvStride = 4u * 64u * FSTR * 4;         // 36864 per stage
    const uint32_t KhB = 0, KlB = 64u * FSTR * 4, VhB = 2u * 64u * FSTR * 4, VlB = 3u * 64u * FSTR * 4;

    const uint32_t aAddr = (uint32_t)((warp * 16 + (lane & 15)) * FSTR + (lane >> 4) * 4) * 4;
    const int bRow = (lane & 7) + ((lane & 16) >> 1);
    const uint32_t bAddr = (uint32_t)(bRow * FSTR + ((lane & 8) ? 4 : 0)) * 4;

    // ---- Q loads: row = t>>1 (0..127), 4 chunks x 2 planes ----
    {
        const int row = t >> 1;
        const int cb  = (t & 1) * 4;
        const __nv_bfloat16* qh = g_qh + (size_t)(s0 + row) * DM + qcol;
        const __nv_bfloat16* ql = g_ql + (size_t)(s0 + row) * DM + qcol;
        uint32_t d = smBase + (uint32_t)(row * FSTR) * 4;
#pragma unroll
        for (int c = 0; c < 4; ++c) {
            cpa16(d + QhB + (cb + c) * 16, qh + (cb + c) * 8);
            cpa16(d + QlB + (cb + c) * 16, ql + (cb + c) * 8);
        }
    }
    // ---- KV stage issue helper data ----
    const int kvRow = t >> 2;          // 0..63
    const int kvCb  = (t & 3) * 2;     // chunk base (2 chunks)
    const __nv_bfloat16* kSrcH = g_kh + (size_t)kvRow * KV_DIM + kcol;
    const __nv_bfloat16* kSrcL = g_kl + (size_t)kvRow * KV_DIM + kcol;
    const __nv_bfloat16* vSrcH = g_vth + (size_t)(kcol + kvRow) * S_LEN;
    const __nv_bfloat16* vSrcL = g_vtl + (size_t)(kcol + kvRow) * S_LEN;
    const uint32_t kvDstRow = (uint32_t)(kvRow * FSTR) * 4;

    // issue stage 0 (k0 = 0)
    {
        uint32_t sb = smBase + kvBase + kvDstRow;
#pragma unroll
        for (int c = 0; c < 2; ++c) {
            cpa16(sb + KhB + (kvCb + c) * 16, kSrcH + (size_t)0 * KV_DIM + (kvCb + c) * 8);
            cpa16(sb + KlB + (kvCb + c) * 16, kSrcL + (size_t)0 * KV_DIM + (kvCb + c) * 8);
            cpa16(sb + VhB + (kvCb + c) * 16, vSrcH + 0 + (kvCb + c) * 8);
            cpa16(sb + VlB + (kvCb + c) * 16, vSrcL + 0 + (kvCb + c) * 8);
        }
        cp_commit();
    }

    float o[8][4];
#pragma unroll
    for (int j = 0; j < 8; ++j)
#pragma unroll
        for (int k = 0; k < 4; ++k) o[j][k] = 0.f;
    float mrow[2] = {-INFINITY, -INFINITY};
    float lrow[2] = {0.f, 0.f};

    const int NIT = S_LEN / 64;
    for (int it = 0; it < NIT; ++it) {
        if (it + 1 < NIT) {
            const int k0 = (it + 1) * 64;
            uint32_t sb = smBase + kvBase + (uint32_t)((it + 1) & 1) * kvStride + kvDstRow;
#pragma unroll
            for (int c = 0; c < 2; ++c) {
                cpa16(sb + KhB + (kvCb + c) * 16, kSrcH + (size_t)k0 * KV_DIM + (kvCb + c) * 8);
                cpa16(sb + KlB + (kvCb + c) * 16, kSrcL + (size_t)k0 * KV_DIM + (kvCb + c) * 8);
                cpa16(sb + VhB + (kvCb + c) * 16, vSrcH + k0 + (kvCb + c) * 8);
                cpa16(sb + VlB + (kvCb + c) * 16, vSrcL + k0 + (kvCb + c) * 8);
            }
            cp_commit();
            cp_wait1();
        } else {
            cp_wait0();
        }
        __syncthreads();

        const uint32_t kb = smBase + kvBase + (uint32_t)(it & 1) * kvStride;

        // ---- S = Q K^T ----
        float s[8][4];
#pragma unroll
        for (int j = 0; j < 8; ++j)
#pragma unroll
            for (int k = 0; k < 4; ++k) s[j][k] = 0.f;

#pragma unroll
        for (int g = 0; g < 4; ++g) {
            const uint32_t gB = (uint32_t)(g * 8) * 4;
            uint32_t ah[4], al[4];
            ldsm4(ah, smBase + QhB + aAddr + gB);
            ldsm4(al, smBase + QlB + aAddr + gB);
#pragma unroll
            for (int jj = 0; jj < 4; ++jj) {
                const uint32_t ro = (uint32_t)(jj * 16 * FSTR) * 4;
                uint32_t bh[4], bl[4];
                ldsm4(bh, kb + KhB + bAddr + ro + gB);
                ldsm4(bl, kb + KlB + bAddr + ro + gB);
#pragma unroll
                for (int hf = 0; hf < 2; ++hf) {
                    mma_bf16(s[jj * 2 + hf], al, bh + hf * 2);
                    mma_bf16(s[jj * 2 + hf], ah, bl + hf * 2);
                    mma_bf16(s[jj * 2 + hf], ah, bh + hf * 2);
                }
            }
        }

        // ---- online softmax ----
        float mx0 = -INFINITY, mx1 = -INFINITY;
#pragma unroll
        for (int jn = 0; jn < 8; ++jn) {
            mx0 = fmaxf(mx0, fmaxf(s[jn][0], s[jn][1]));
            mx1 = fmaxf(mx1, fmaxf(s[jn][2], s[jn][3]));
        }
        mx0 = fmaxf(mx0, __shfl_xor_sync(0xffffffffu, mx0, 1));
        mx0 = fmaxf(mx0, __shfl_xor_sync(0xffffffffu, mx0, 2));
        mx1 = fmaxf(mx1, __shfl_xor_sync(0xffffffffu, mx1, 1));
        mx1 = fmaxf(mx1, __shfl_xor_sync(0xffffffffu, mx1, 2));

        const float mn0 = fmaxf(mrow[0], mx0);
        const float mn1 = fmaxf(mrow[1], mx1);
        const float a0 = __expf(mrow[0] - mn0);
        const float a1 = __expf(mrow[1] - mn1);
        float rs0 = 0.f, rs1 = 0.f;
#pragma unroll
        for (int jn = 0; jn < 8; ++jn) {
            s[jn][0] = __expf(s[jn][0] - mn0); rs0 += s[jn][0];
            s[jn][1] = __expf(s[jn][1] - mn0); rs0 += s[jn][1];
            s[jn][2] = __expf(s[jn][2] - mn1); rs1 += s[jn][2];
            s[jn][3] = __expf(s[jn][3] - mn1); rs1 += s[jn][3];
        }
        rs0 += __shfl_xor_sync(0xffffffffu, rs0, 1);
        rs0 += __shfl_xor_sync(0xffffffffu, rs0, 2);
        rs1 += __shfl_xor_sync(0xffffffffu, rs1, 1);
        rs1 += __shfl_xor_sync(0xffffffffu, rs1, 2);

        lrow[0] = lrow[0] * a0 + rs0;
        lrow[1] = lrow[1] * a1 + rs1;
        mrow[0] = mn0;
        mrow[1] = mn1;
#pragma unroll
        for (int jn = 0; jn < 8; ++jn) {
            o[jn][0] *= a0; o[jn][1] *= a0;
            o[jn][2] *= a1; o[jn][3] *= a1;
        }

        // ---- O += P V (V^T fragments same pattern as K) ----
#pragma unroll
        for (int g = 0; g < 4; ++g) {
            uint32_t ph[4], pl[4];
            split_pair(s[2 * g][0],     s[2 * g][1],     ph[0], pl[0]);
            split_pair(s[2 * g][2],     s[2 * g][3],     ph[1], pl[1]);
            split_pair(s[2 * g + 1][0], s[2 * g + 1][1], ph[2], pl[2]);
            split_pair(s[2 * g + 1][2], s[2 * g + 1][3], ph[3], pl[3]);
            const uint32_t gB = (uint32_t)(g * 8) * 4;
#pragma unroll
            for (int jj = 0; jj < 4; ++jj) {
                const uint32_t ro = (uint32_t)(jj * 16 * FSTR) * 4;
                uint32_t vh[4], vl[4];
                ldsm4(vh, kb + VhB + bAddr + ro + gB);
                ldsm4(vl, kb + VlB + bAddr + ro + gB);
#pragma unroll
                for (int hf = 0; hf < 2; ++hf) {
                    mma_bf16(o[jj * 2 + hf], pl, vh + hf * 2);
                    mma_bf16(o[jj * 2 + hf], ph, vl + hf * 2);
                    mma_bf16(o[jj * 2 + hf], ph, vh + hf * 2);
                }
            }
        }
        __syncthreads();   // buffer consumed before refill
    }

    // ---- normalize + write planes ----
    const float inv0 = 1.0f / lrow[0];
    const float inv1 = 1.0f / lrow[1];
    const int row0 = s0 + warp * 16 + r4;
#pragma unroll
    for (int jn = 0; jn < 8; ++jn) {
        const int col = qcol + jn * 8 + c4 * 2;
        uint32_t hh, ll;
        split_pair(o[jn][0] * inv0, o[jn][1] * inv0, hh, ll);
        *(uint32_t*)&g_ah[(size_t)row0 * DM + col] = hh;
        *(uint32_t*)&g_al[(size_t)row0 * DM + col] = ll;
        split_pair(o[jn][2] * inv1, o[jn][3] * inv1, hh, ll);
        *(uint32_t*)&g_ah[(size_t)(row0 + 8) * DM + col] = hh;
        *(uint32_t*)&g_al[(size_t)(row0 + 8) * DM + col] = ll;
    }
}

// ---------------- launch ----------------
extern "C" void kernel_launch(void* const* d_in, const int* in_sizes, int n_in,
                              void* d_out, int out_size)
{
    const float *x, *Wq, *Wk, *Wv, *Wo;
    if (in_sizes[0] == S_LEN * DM) {        // dict order [x, Wq, Wk, Wv, Wo]
        x  = (const float*)d_in[0];
        Wq = (const float*)d_in[1];
        Wk = (const float*)d_in[2];
        Wv = (const float*)d_in[3];
        Wo = (const float*)d_in[4];
    } else {                                 // sorted order [Wk, Wo, Wq, Wv, x]
        Wk = (const float*)d_in[0];
        Wo = (const float*)d_in[1];
        Wq = (const float*)d_in[2];
        Wv = (const float*)d_in[3];
        x  = (const float*)d_in[4];
    }
    float* out = (float*)d_out;

    float *rc, *rs;
    cudaGetSymbolAddress((void**)&rc, g_rc);
    cudaGetSymbolAddress((void**)&rs, g_rs);
    __nv_bfloat16 *xh, *xl, *wh, *wl, *woh, *wol, *qkvh, *qkvl, *ah, *al;
    cudaGetSymbolAddress((void**)&xh, g_xh);   cudaGetSymbolAddress((void**)&xl, g_xl);
    cudaGetSymbolAddress((void**)&wh, g_wh);   cudaGetSymbolAddress((void**)&wl, g_wl);
    cudaGetSymbolAddress((void**)&woh, g_woh); cudaGetSymbolAddress((void**)&wol, g_wol);
    cudaGetSymbolAddress((void**)&qkvh, g_qkvh); cudaGetSymbolAddress((void**)&qkvl, g_qkvl);
    cudaGetSymbolAddress((void**)&ah, g_ah);   cudaGetSymbolAddress((void**)&al, g_al);

    const int gemm_smem = 2 * 4 * GTILE * sizeof(uint32_t);                      // 49152
    const int fa_smem   = (2 * 128 + 2 * 4 * 64) * FSTR * sizeof(uint32_t);      // 110592
    cudaFuncSetAttribute(gemm_planes, cudaFuncAttributeMaxDynamicSharedMemorySize, gemm_smem);
    cudaFuncSetAttribute(fa_tc, cudaFuncAttributeMaxDynamicSharedMemorySize, fa_smem);

    // 1: rope table
    rope_table<<<(S_LEN * 32 + 255) / 256, 256>>>(rc, rs);

    // 2: convert inputs to bf16 hi/lo planes
    conv_all<<<(QTOT + 255) / 256, 256>>>(x, Wq, Wk, Wv, Wo);

    // 3: fused QKV projection (planes -> planes)
    gemm_planes<<<dim3(QKV_N / 128, S_LEN / 128), 256, gemm_smem>>>(
        xh, xl, wh, wl, nullptr, qkvh, qkvl, S_LEN, QKV_N, DM);

    // 4: rope + scale -> Q/K planes
    rope_qk_planes<<<(S_LEN * 1280 + 255) / 256, 256>>>(rc, rs);

    // 5: V transpose -> Vt planes
    vt_transpose<<<dim3(S_LEN / 32, KV_DIM / 32), dim3(32, 8)>>>();

    // 6: flash attention
    fa_tc<<<dim3(S_LEN / 128, NHEADS), 256, fa_smem>>>();

    // 7: output projection (planes -> f32 out)
    gemm_planes<<<dim3(DM / 128, S_LEN / 128), 256, gemm_smem>>>(
        ah, al, woh, wol, out, nullptr, nullptr, S_LEN, DM, DM);
}

// round 8
// speedup vs baseline: 4.5637x; 1.3113x over previous
#include <cuda_runtime.h>
#include <cuda_fp16.h>
#include <math.h>
#include <stdint.h>

#define S_LEN   2048
#define DM      2048
#define KV_DIM  512
#define NHEADS  32
#define NKVH    8
#define HDIM    64
#define QKV_N   3072

// ---------------- fp16 hi/lo planes (allocation-free scratch) ----------------
__device__ __half g_xh[S_LEN * DM];                              // x hi only (A operand)
__device__ __half g_wh[QKV_N * DM],  g_wl[QKV_N * DM];           // Wq|Wk|Wv hi+lo
__device__ __half g_woh[DM * DM],    g_wol[DM * DM];             // Wo hi+lo
__device__ __half g_qkvh[S_LEN * QKV_N], g_qkvl[S_LEN * QKV_N];  // proj out hi+lo
__device__ __half g_qh[S_LEN * DM];                              // roped+scaled Q hi only
__device__ __half g_kh[S_LEN * KV_DIM], g_kl[S_LEN * KV_DIM];    // roped K hi+lo
__device__ __half g_vth[KV_DIM * S_LEN], g_vtl[KV_DIM * S_LEN];  // V^T hi+lo
__device__ __half g_ah[S_LEN * DM];                              // attn out hi only
__device__ float g_rc[S_LEN * 32], g_rs[S_LEN * 32];

// ---------------- helpers ----------------
__device__ __forceinline__ uint32_t pack_h2(float e0, float e1) {
    __half2 h = __floats2half2_rn(e0, e1);   // e0 -> low 16 bits
    return *(uint32_t*)&h;
}
__device__ __forceinline__ void split_h2(float x0, float x1, uint32_t& h, uint32_t& l) {
    float h0 = __half2float(__float2half_rn(x0));
    float h1 = __half2float(__float2half_rn(x1));
    h = pack_h2(h0, h1);
    l = pack_h2(x0 - h0, x1 - h1);
}
__device__ __forceinline__ void mma_f16(float* c, const uint32_t* a, const uint32_t* b) {
    asm volatile(
        "mma.sync.aligned.m16n8k16.row.col.f32.f16.f16.f32 "
        "{%0,%1,%2,%3}, {%4,%5,%6,%7}, {%8,%9}, {%0,%1,%2,%3};"
        : "+f"(c[0]), "+f"(c[1]), "+f"(c[2]), "+f"(c[3])
        : "r"(a[0]), "r"(a[1]), "r"(a[2]), "r"(a[3]), "r"(b[0]), "r"(b[1]));
}
__device__ __forceinline__ void ldsm4(uint32_t* r, uint32_t addr) {
    asm volatile("ldmatrix.sync.aligned.m8n8.x4.shared.b16 {%0,%1,%2,%3}, [%4];"
        : "=r"(r[0]), "=r"(r[1]), "=r"(r[2]), "=r"(r[3]) : "r"(addr));
}
__device__ __forceinline__ void cpa16(uint32_t dst, const void* src) {
    asm volatile("cp.async.cg.shared.global [%0], [%1], 16;" :: "r"(dst), "l"(src));
}
__device__ __forceinline__ void cp_commit() { asm volatile("cp.async.commit_group;"); }
__device__ __forceinline__ void cp_wait0()  { asm volatile("cp.async.wait_group 0;"); }
__device__ __forceinline__ void cp_wait1()  { asm volatile("cp.async.wait_group 1;"); }

// ---------------- input conversion ----------------
#define QX   (S_LEN * DM / 4)
#define QWQ  (DM * DM / 4)
#define QWK  (KV_DIM * DM / 4)
#define QWV  (KV_DIM * DM / 4)
#define QWO  (DM * DM / 4)
#define QTOT (QX + QWQ + QWK + QWV + QWO)

__global__ void conv_all(const float* __restrict__ x,  const float* __restrict__ wq,
                         const float* __restrict__ wk, const float* __restrict__ wv,
                         const float* __restrict__ wo)
{
    int q = blockIdx.x * blockDim.x + threadIdx.x;
    if (q >= QTOT) return;
    const float* src;
    __half *dh, *dl;
    int lq;
    if (q < QX)                        { src = x;  dh = g_xh;  dl = nullptr; lq = q; }
    else if (q < QX + QWQ)             { src = wq; dh = g_wh;  dl = g_wl;   lq = q - QX; }
    else if (q < QX + QWQ + QWK)       { src = wk; dh = g_wh + DM * DM; dl = g_wl + DM * DM; lq = q - QX - QWQ; }
    else if (q < QX + QWQ + QWK + QWV) { src = wv; dh = g_wh + DM * DM + KV_DIM * DM; dl = g_wl + DM * DM + KV_DIM * DM; lq = q - QX - QWQ - QWK; }
    else                               { src = wo; dh = g_woh; dl = g_wol;  lq = q - QX - QWQ - QWK - QWV; }

    float4 v = ((const float4*)src)[lq];
    uint32_t h0, l0, h1, l1;
    split_h2(v.x, v.y, h0, l0);
    split_h2(v.z, v.w, h1, l1);
    ((uint32_t*)dh)[lq * 2] = h0; ((uint32_t*)dh)[lq * 2 + 1] = h1;
    if (dl) { ((uint32_t*)dl)[lq * 2] = l0; ((uint32_t*)dl)[lq * 2 + 1] = l1; }
}

// ---------------- fp16x2 GEMM: C[M,N] = A[M,K] @ B[N,K]^T ----------------
// A: hi plane only. B: hi+lo planes. BM=BN=128, BK=16, 256 thr (8 warps 4m x 2n).
#define GSTR 12                 // uints per smem row (8 data + 4 pad)
#define GTILE (128 * GSTR)

__global__ __launch_bounds__(256, 2) void gemm_h2(
    const __half* __restrict__ Ah,
    const __half* __restrict__ Bh, const __half* __restrict__ Bl,
    float* __restrict__ Cf, __half* __restrict__ Ch, __half* __restrict__ Cl,
    int M, int N, int K)
{
    extern __shared__ uint32_t gsm[];

    const int t    = threadIdx.x;
    const int lane = t & 31;
    const int warp = t >> 5;
    const int wm   = warp >> 1;
    const int wn   = warp & 1;
    const int m0   = blockIdx.y * 128;
    const int n0   = blockIdx.x * 128;

    const int lrow  = t >> 1;
    const int lhalf = t & 1;

    uint32_t smBase = (uint32_t)__cvta_generic_to_shared(gsm);
    const uint32_t aHiB = 0, bHiB = GTILE * 4, bLoB = 2u * GTILE * 4;
    const uint32_t bufStride = 3u * GTILE * 4;

    const uint32_t ldDst = (uint32_t)(lrow * GSTR + lhalf * 4) * 4;

    const uint32_t aAddr = (uint32_t)((wm * 32 + (lane & 15)) * GSTR + (lane >> 4) * 4) * 4;
    const int bRow = wn * 64 + (lane & 7) + ((lane & 16) >> 1);
    const uint32_t bAddr = (uint32_t)(bRow * GSTR + ((lane & 8) ? 4 : 0)) * 4;

    const __half* aSrcH = Ah + (size_t)(m0 + lrow) * K + lhalf * 8;
    const __half* bSrcH = Bh + (size_t)(n0 + lrow) * K + lhalf * 8;
    const __half* bSrcL = Bl + (size_t)(n0 + lrow) * K + lhalf * 8;

    float acc[2][8][4];
#pragma unroll
    for (int i = 0; i < 2; ++i)
#pragma unroll
        for (int j = 0; j < 8; ++j)
#pragma unroll
            for (int k = 0; k < 4; ++k) acc[i][j][k] = 0.f;

    const int nt = K / 16;

    {   // prologue
        uint32_t d = smBase + ldDst;
        cpa16(d + aHiB, aSrcH);
        cpa16(d + bHiB, bSrcH);
        cpa16(d + bLoB, bSrcL);
        cp_commit();
    }

    for (int tt = 0; tt < nt; ++tt) {
        if (tt + 1 < nt) {
            const int k0 = (tt + 1) * 16;
            uint32_t d = smBase + (uint32_t)((tt + 1) & 1) * bufStride + ldDst;
            cpa16(d + aHiB, aSrcH + k0);
            cpa16(d + bHiB, bSrcH + k0);
            cpa16(d + bLoB, bSrcL + k0);
            cp_commit();
            cp_wait1();
        } else {
            cp_wait0();
        }
        __syncthreads();

        const uint32_t bb = smBase + (uint32_t)(tt & 1) * bufStride;

        uint32_t ah[2][4];
#pragma unroll
        for (int im = 0; im < 2; ++im)
            ldsm4(ah[im], bb + aHiB + aAddr + (uint32_t)(im * 16 * GSTR) * 4);

#pragma unroll
        for (int jj = 0; jj < 4; ++jj) {
            uint32_t bh[4], bl[4];
            const uint32_t ro = (uint32_t)(jj * 16 * GSTR) * 4;
            ldsm4(bh, bb + bHiB + bAddr + ro);
            ldsm4(bl, bb + bLoB + bAddr + ro);
#pragma unroll
            for (int hf = 0; hf < 2; ++hf) {
                const int ntile = jj * 2 + hf;
#pragma unroll
                for (int im = 0; im < 2; ++im) {
                    mma_f16(acc[im][ntile], ah[im], bl + hf * 2);
                    mma_f16(acc[im][ntile], ah[im], bh + hf * 2);
                }
            }
        }
        __syncthreads();
    }

    // epilogue
    const int r4 = lane >> 2;
    const int c4 = lane & 3;
    const int crow0 = m0 + wm * 32 + r4;
    const int ccol0 = n0 + wn * 64 + c4 * 2;
#pragma unroll
    for (int im = 0; im < 2; ++im) {
#pragma unroll
        for (int jn = 0; jn < 8; ++jn) {
            const int row = crow0 + im * 16;
            const int col = ccol0 + jn * 8;
            float v0 = acc[im][jn][0], v1 = acc[im][jn][1];
            float v2 = acc[im][jn][2], v3 = acc[im][jn][3];
            if (Cf) {
                *(float2*)&Cf[(size_t)row * N + col]       = make_float2(v0, v1);
                *(float2*)&Cf[(size_t)(row + 8) * N + col] = make_float2(v2, v3);
            } else {
                uint32_t h, l;
                split_h2(v0, v1, h, l);
                *(uint32_t*)&Ch[(size_t)row * N + col] = h;
                *(uint32_t*)&Cl[(size_t)row * N + col] = l;
                split_h2(v2, v3, h, l);
                *(uint32_t*)&Ch[(size_t)(row + 8) * N + col] = h;
                *(uint32_t*)&Cl[(size_t)(row + 8) * N + col] = l;
            }
        }
    }
}

// ---------------- RoPE table ----------------
__global__ void rope_table(float* __restrict__ rc, float* __restrict__ rs)
{
    int idx = blockIdx.x * blockDim.x + threadIdx.x;
    if (idx >= S_LEN * 32) return;
    int s = idx >> 5;
    int i = idx & 31;
    double ang = (double)s * pow(10000.0, -(double)i / 32.0);
    double sd, cd;
    sincos(ang, &sd, &cd);
    rc[idx] = (float)cd;
    rs[idx] = (float)sd;
}

// ---------------- RoPE + scale on QKV planes ----------------
__global__ void rope_qk_planes(const float* __restrict__ rc, const float* __restrict__ rs)
{
    int idx = blockIdx.x * blockDim.x + threadIdx.x;
    const int per_row = 1280;   // 1024 Q pairs + 256 K pairs
    if (idx >= S_LEN * per_row) return;
    int s = idx / per_row;
    int r = idx - s * per_row;

    float c, sn;
    if (r < 1024) {        // Q -> hi only, scaled
        int head = r >> 5, i = r & 31;
        int col = head * 64 + i;
        c  = rc[(s << 5) + i];
        sn = rs[(s << 5) + i];
        size_t b1 = (size_t)s * QKV_N + col;
        float x1 = __half2float(g_qkvh[b1])      + __half2float(g_qkvl[b1]);
        float x2 = __half2float(g_qkvh[b1 + 32]) + __half2float(g_qkvl[b1 + 32]);
        float y1 = (x1 * c - x2 * sn) * 0.125f;
        float y2 = (x2 * c + x1 * sn) * 0.125f;
        size_t d1 = (size_t)s * DM + col;
        g_qh[d1]      = __float2half_rn(y1);
        g_qh[d1 + 32] = __float2half_rn(y2);
    } else {               // K -> hi+lo
        int rr = r - 1024;
        int kvh = rr >> 5, i = rr & 31;
        c  = rc[(s << 5) + i];
        sn = rs[(s << 5) + i];
        size_t b1 = (size_t)s * QKV_N + 2048 + kvh * 64 + i;
        float x1 = __half2float(g_qkvh[b1])      + __half2float(g_qkvl[b1]);
        float x2 = __half2float(g_qkvh[b1 + 32]) + __half2float(g_qkvl[b1 + 32]);
        float y1 = x1 * c - x2 * sn;
        float y2 = x2 * c + x1 * sn;
        size_t d1 = (size_t)s * KV_DIM + kvh * 64 + i;
        __half h1 = __float2half_rn(y1), h2 = __float2half_rn(y2);
        g_kh[d1]      = h1; g_kl[d1]      = __float2half_rn(y1 - __half2float(h1));
        g_kh[d1 + 32] = h2; g_kl[d1 + 32] = __float2half_rn(y2 - __half2float(h2));
    }
}

// ---------------- V transpose: QKV cols [2560,3072) -> Vt[c][s] hi+lo ----------------
__global__ void vt_transpose()
{
    __shared__ __half th[32][33], tl[32][33];
    const int tx = threadIdx.x, ty = threadIdx.y;   // (32, 8)
    const int s0 = blockIdx.x * 32;
    const int c0 = blockIdx.y * 32;
#pragma unroll
    for (int k = 0; k < 4; ++k) {
        int s = s0 + ty + k * 8;
        th[ty + k * 8][tx] = g_qkvh[(size_t)s * QKV_N + 2560 + c0 + tx];
        tl[ty + k * 8][tx] = g_qkvl[(size_t)s * QKV_N + 2560 + c0 + tx];
    }
    __syncthreads();
#pragma unroll
    for (int k = 0; k < 4; ++k) {
        int c = c0 + ty + k * 8;
        g_vth[(size_t)c * S_LEN + s0 + tx] = th[tx][ty + k * 8];
        g_vtl[(size_t)c * S_LEN + s0 + tx] = tl[tx][ty + k * 8];
    }
}

// ---------------- Flash attention: fp16x2, cp.async double-buffered KV ----------------
#define FSTR 36   // uints per smem row (32 data + 4 pad)

__global__ __launch_bounds__(256) void fa_tc()
{
    extern __shared__ uint32_t fsm[];

    const int t    = threadIdx.x;
    const int lane = t & 31;
    const int warp = t >> 5;
    const int r4   = lane >> 2;
    const int c4   = lane & 3;
    const int s0   = blockIdx.x * 128;
    const int h    = blockIdx.y;
    const int kvh  = h / (NHEADS / NKVH);
    const int qcol = h * HDIM;
    const int kcol = kvh * HDIM;

    uint32_t smBase = (uint32_t)__cvta_generic_to_shared(fsm);
    const uint32_t QhB = 0;
    const uint32_t kvBase = 128u * FSTR * 4;
    const uint32_t kvStride = 4u * 64u * FSTR * 4;
    const uint32_t KhB = 0, KlB = 64u * FSTR * 4, VhB = 2u * 64u * FSTR * 4, VlB = 3u * 64u * FSTR * 4;

    const uint32_t aAddr = (uint32_t)((warp * 16 + (lane & 15)) * FSTR + (lane >> 4) * 4) * 4;
    const int bRow = (lane & 7) + ((lane & 16) >> 1);
    const uint32_t bAddr = (uint32_t)(bRow * FSTR + ((lane & 8) ? 4 : 0)) * 4;

    // ---- Q hi loads: 128 rows x 8 chunks, 256 threads -> 4 chunks each ----
    {
        const int row = t >> 1;
        const int cb  = (t & 1) * 4;
        const __half* qh = g_qh + (size_t)(s0 + row) * DM + qcol;
        uint32_t d = smBase + QhB + (uint32_t)(row * FSTR) * 4;
#pragma unroll
        for (int c = 0; c < 4; ++c)
            cpa16(d + (cb + c) * 16, qh + (cb + c) * 8);
    }

    const int kvRow = t >> 2;
    const int kvCb  = (t & 3) * 2;
    const __half* kSrcH = g_kh + (size_t)kvRow * KV_DIM + kcol;
    const __half* kSrcL = g_kl + (size_t)kvRow * KV_DIM + kcol;
    const __half* vSrcH = g_vth + (size_t)(kcol + kvRow) * S_LEN;
    const __half* vSrcL = g_vtl + (size_t)(kcol + kvRow) * S_LEN;
    const uint32_t kvDstRow = (uint32_t)(kvRow * FSTR) * 4;

    {   // stage 0
        uint32_t sb = smBase + kvBase + kvDstRow;
#pragma unroll
        for (int c = 0; c < 2; ++c) {
            cpa16(sb + KhB + (kvCb + c) * 16, kSrcH + (kvCb + c) * 8);
            cpa16(sb + KlB + (kvCb + c) * 16, kSrcL + (kvCb + c) * 8);
            cpa16(sb + VhB + (kvCb + c) * 16, vSrcH + (kvCb + c) * 8);
            cpa16(sb + VlB + (kvCb + c) * 16, vSrcL + (kvCb + c) * 8);
        }
        cp_commit();
    }

    float o[8][4];
#pragma unroll
    for (int j = 0; j < 8; ++j)
#pragma unroll
        for (int k = 0; k < 4; ++k) o[j][k] = 0.f;
    float mrow[2] = {-INFINITY, -INFINITY};
    float lrow[2] = {0.f, 0.f};

    const int NIT = S_LEN / 64;
    for (int it = 0; it < NIT; ++it) {
        if (it + 1 < NIT) {
            const int k0 = (it + 1) * 64;
            uint32_t sb = smBase + kvBase + (uint32_t)((it + 1) & 1) * kvStride + kvDstRow;
#pragma unroll
            for (int c = 0; c < 2; ++c) {
                cpa16(sb + KhB + (kvCb + c) * 16, kSrcH + (size_t)k0 * KV_DIM + (kvCb + c) * 8);
                cpa16(sb + KlB + (kvCb + c) * 16, kSrcL + (size_t)k0 * KV_DIM + (kvCb + c) * 8);
                cpa16(sb + VhB + (kvCb + c) * 16, vSrcH + k0 + (kvCb + c) * 8);
                cpa16(sb + VlB + (kvCb + c) * 16, vSrcL + k0 + (kvCb + c) * 8);
            }
            cp_commit();
            cp_wait1();
        } else {
            cp_wait0();
        }
        __syncthreads();

        const uint32_t kb = smBase + kvBase + (uint32_t)(it & 1) * kvStride;

        // ---- S = Q K^T ----
        float s[8][4];
#pragma unroll
        for (int j = 0; j < 8; ++j)
#pragma unroll
            for (int k = 0; k < 4; ++k) s[j][k] = 0.f;

#pragma unroll
        for (int g = 0; g < 4; ++g) {
            const uint32_t gB = (uint32_t)(g * 8) * 4;
            uint32_t ah[4];
            ldsm4(ah, smBase + QhB + aAddr + gB);
#pragma unroll
            for (int jj = 0; jj < 4; ++jj) {
                const uint32_t ro = (uint32_t)(jj * 16 * FSTR) * 4;
                uint32_t bh[4], bl[4];
                ldsm4(bh, kb + KhB + bAddr + ro + gB);
                ldsm4(bl, kb + KlB + bAddr + ro + gB);
#pragma unroll
                for (int hf = 0; hf < 2; ++hf) {
                    mma_f16(s[jj * 2 + hf], ah, bl + hf * 2);
                    mma_f16(s[jj * 2 + hf], ah, bh + hf * 2);
                }
            }
        }

        // ---- online softmax ----
        float mx0 = -INFINITY, mx1 = -INFINITY;
#pragma unroll
        for (int jn = 0; jn < 8; ++jn) {
            mx0 = fmaxf(mx0, fmaxf(s[jn][0], s[jn][1]));
            mx1 = fmaxf(mx1, fmaxf(s[jn][2], s[jn][3]));
        }
        mx0 = fmaxf(mx0, __shfl_xor_sync(0xffffffffu, mx0, 1));
        mx0 = fmaxf(mx0, __shfl_xor_sync(0xffffffffu, mx0, 2));
        mx1 = fmaxf(mx1, __shfl_xor_sync(0xffffffffu, mx1, 1));
        mx1 = fmaxf(mx1, __shfl_xor_sync(0xffffffffu, mx1, 2));

        const float mn0 = fmaxf(mrow[0], mx0);
        const float mn1 = fmaxf(mrow[1], mx1);
        const float a0 = __expf(mrow[0] - mn0);
        const float a1 = __expf(mrow[1] - mn1);
        float rs0 = 0.f, rs1 = 0.f;
#pragma unroll
        for (int jn = 0; jn < 8; ++jn) {
            s[jn][0] = __expf(s[jn][0] - mn0); rs0 += s[jn][0];
            s[jn][1] = __expf(s[jn][1] - mn0); rs0 += s[jn][1];
            s[jn][2] = __expf(s[jn][2] - mn1); rs1 += s[jn][2];
            s[jn][3] = __expf(s[jn][3] - mn1); rs1 += s[jn][3];
        }
        rs0 += __shfl_xor_sync(0xffffffffu, rs0, 1);
        rs0 += __shfl_xor_sync(0xffffffffu, rs0, 2);
        rs1 += __shfl_xor_sync(0xffffffffu, rs1, 1);
        rs1 += __shfl_xor_sync(0xffffffffu, rs1, 2);

        lrow[0] = lrow[0] * a0 + rs0;
        lrow[1] = lrow[1] * a1 + rs1;
        mrow[0] = mn0;
        mrow[1] = mn1;
#pragma unroll
        for (int jn = 0; jn < 8; ++jn) {
            o[jn][0] *= a0; o[jn][1] *= a0;
            o[jn][2] *= a1; o[jn][3] *= a1;
        }

        // ---- O += P V : P = fp16(s), no residual ----
#pragma unroll
        for (int g = 0; g < 4; ++g) {
            uint32_t ph[4];
            ph[0] = pack_h2(s[2 * g][0],     s[2 * g][1]);
            ph[1] = pack_h2(s[2 * g][2],     s[2 * g][3]);
            ph[2] = pack_h2(s[2 * g + 1][0], s[2 * g + 1][1]);
            ph[3] = pack_h2(s[2 * g + 1][2], s[2 * g + 1][3]);
            const uint32_t gB = (uint32_t)(g * 8) * 4;
#pragma unroll
            for (int jj = 0; jj < 4; ++jj) {
                const uint32_t ro = (uint32_t)(jj * 16 * FSTR) * 4;
                uint32_t vh[4], vl[4];
                ldsm4(vh, kb + VhB + bAddr + ro + gB);
                ldsm4(vl, kb + VlB + bAddr + ro + gB);
#pragma unroll
                for (int hf = 0; hf < 2; ++hf) {
                    mma_f16(o[jj * 2 + hf], ph, vl + hf * 2);
                    mma_f16(o[jj * 2 + hf], ph, vh + hf * 2);
                }
            }
        }
        __syncthreads();
    }

    // ---- normalize + write hi plane ----
    const float inv0 = 1.0f / lrow[0];
    const float inv1 = 1.0f / lrow[1];
    const int row0 = s0 + warp * 16 + r4;
#pragma unroll
    for (int jn = 0; jn < 8; ++jn) {
        const int col = qcol + jn * 8 + c4 * 2;
        *(uint32_t*)&g_ah[(size_t)row0 * DM + col] =
            pack_h2(o[jn][0] * inv0, o[jn][1] * inv0);
        *(uint32_t*)&g_ah[(size_t)(row0 + 8) * DM + col] =
            pack_h2(o[jn][2] * inv1, o[jn][3] * inv1);
    }
}

// ---------------- launch ----------------
extern "C" void kernel_launch(void* const* d_in, const int* in_sizes, int n_in,
                              void* d_out, int out_size)
{
    const float *x, *Wq, *Wk, *Wv, *Wo;
    if (in_sizes[0] == S_LEN * DM) {        // dict order [x, Wq, Wk, Wv, Wo]
        x  = (const float*)d_in[0];
        Wq = (const float*)d_in[1];
        Wk = (const float*)d_in[2];
        Wv = (const float*)d_in[3];
        Wo = (const float*)d_in[4];
    } else {                                 // sorted order [Wk, Wo, Wq, Wv, x]
        Wk = (const float*)d_in[0];
        Wo = (const float*)d_in[1];
        Wq = (const float*)d_in[2];
        Wv = (const float*)d_in[3];
        x  = (const float*)d_in[4];
    }
    float* out = (float*)d_out;

    float *rc, *rs;
    cudaGetSymbolAddress((void**)&rc, g_rc);
    cudaGetSymbolAddress((void**)&rs, g_rs);
    __half *xh, *wh, *wl, *woh, *wol, *qkvh, *qkvl, *ah;
    cudaGetSymbolAddress((void**)&xh, g_xh);
    cudaGetSymbolAddress((void**)&wh, g_wh);   cudaGetSymbolAddress((void**)&wl, g_wl);
    cudaGetSymbolAddress((void**)&woh, g_woh); cudaGetSymbolAddress((void**)&wol, g_wol);
    cudaGetSymbolAddress((void**)&qkvh, g_qkvh); cudaGetSymbolAddress((void**)&qkvl, g_qkvl);
    cudaGetSymbolAddress((void**)&ah, g_ah);

    const int gemm_smem = 2 * 3 * GTILE * sizeof(uint32_t);                 // 36864
    const int fa_smem   = (128 + 2 * 4 * 64) * FSTR * sizeof(uint32_t);     // 92160
    cudaFuncSetAttribute(gemm_h2, cudaFuncAttributeMaxDynamicSharedMemorySize, gemm_smem);
    cudaFuncSetAttribute(fa_tc, cudaFuncAttributeMaxDynamicSharedMemorySize, fa_smem);

    // 1: rope table
    rope_table<<<(S_LEN * 32 + 255) / 256, 256>>>(rc, rs);

    // 2: convert inputs to fp16 planes
    conv_all<<<(QTOT + 255) / 256, 256>>>(x, Wq, Wk, Wv, Wo);

    // 3: fused QKV projection
    gemm_h2<<<dim3(QKV_N / 128, S_LEN / 128), 256, gemm_smem>>>(
        xh, wh, wl, nullptr, qkvh, qkvl, S_LEN, QKV_N, DM);

    // 4: rope + scale
    rope_qk_planes<<<(S_LEN * 1280 + 255) / 256, 256>>>(rc, rs);

    // 5: V transpose
    vt_transpose<<<dim3(S_LEN / 32, KV_DIM / 32), dim3(32, 8)>>>();

    // 6: flash attention (profiled launch)
    fa_tc<<<dim3(S_LEN / 128, NHEADS), 256, fa_smem>>>();

    // 7: output projection
    gemm_h2<<<dim3(DM / 128, S_LEN / 128), 256, gemm_smem>>>(
        ah, woh, wol, out, nullptr, nullptr, S_LEN, DM, DM);
}

// round 10
// speedup vs baseline: 4.7244x; 1.0352x over previous
#include <cuda_runtime.h>
#include <cuda_fp16.h>
#include <math.h>
#include <stdint.h>

#define S_LEN   2048
#define DM      2048
#define KV_DIM  512
#define NHEADS  32
#define NKVH    8
#define HDIM    64
#define QKV_N   3072

// ---------------- fp16 hi/lo planes ----------------
__device__ __half g_xh[S_LEN * DM];                              // x hi only (A operand)
__device__ __half g_wh[QKV_N * DM],  g_wl[QKV_N * DM];           // Wq|Wk|Wv hi+lo
__device__ __half g_woh[DM * DM],    g_wol[DM * DM];             // Wo hi+lo
__device__ __half g_qkvh[S_LEN * QKV_N], g_qkvl[S_LEN * QKV_N];  // proj out hi+lo
__device__ __half g_qh[S_LEN * DM];                              // roped+scaled Q hi
__device__ __half g_kh[S_LEN * KV_DIM], g_kl[S_LEN * KV_DIM];    // roped K hi+lo
__device__ __half g_vth[KV_DIM * S_LEN], g_vtl[KV_DIM * S_LEN];  // V^T hi+lo
__device__ __half g_ah[S_LEN * DM];                              // attn out hi
__device__ float g_rc[S_LEN * 32], g_rs[S_LEN * 32];

// ---------------- helpers ----------------
__device__ __forceinline__ uint32_t pack_h2(float e0, float e1) {
    __half2 h = __floats2half2_rn(e0, e1);
    return *(uint32_t*)&h;
}
__device__ __forceinline__ void split_h2(float x0, float x1, uint32_t& h, uint32_t& l) {
    float h0 = __half2float(__float2half_rn(x0));
    float h1 = __half2float(__float2half_rn(x1));
    h = pack_h2(h0, h1);
    l = pack_h2(x0 - h0, x1 - h1);
}
__device__ __forceinline__ void mma_f16(float* c, const uint32_t* a, const uint32_t* b) {
    asm volatile(
        "mma.sync.aligned.m16n8k16.row.col.f32.f16.f16.f32 "
        "{%0,%1,%2,%3}, {%4,%5,%6,%7}, {%8,%9}, {%0,%1,%2,%3};"
        : "+f"(c[0]), "+f"(c[1]), "+f"(c[2]), "+f"(c[3])
        : "r"(a[0]), "r"(a[1]), "r"(a[2]), "r"(a[3]), "r"(b[0]), "r"(b[1]));
}
__device__ __forceinline__ void ldsm4(uint32_t* r, uint32_t addr) {
    asm volatile("ldmatrix.sync.aligned.m8n8.x4.shared.b16 {%0,%1,%2,%3}, [%4];"
        : "=r"(r[0]), "=r"(r[1]), "=r"(r[2]), "=r"(r[3]) : "r"(addr));
}
__device__ __forceinline__ void cpa16(uint32_t dst, const void* src) {
    asm volatile("cp.async.cg.shared.global [%0], [%1], 16;" :: "r"(dst), "l"(src));
}
__device__ __forceinline__ void cp_commit() { asm volatile("cp.async.commit_group;"); }
__device__ __forceinline__ void cp_wait0()  { asm volatile("cp.async.wait_group 0;"); }
__device__ __forceinline__ void cp_wait1()  { asm volatile("cp.async.wait_group 1;"); }

// ---------------- conv (f32 -> fp16 planes) + rope table, fused ----------------
#define QX   (S_LEN * DM / 4)
#define QWQ  (DM * DM / 4)
#define QWK  (KV_DIM * DM / 4)
#define QWV  (KV_DIM * DM / 4)
#define QWO  (DM * DM / 4)
#define QTOT (QX + QWQ + QWK + QWV + QWO)
#define CONV_BLKS ((QTOT + 255) / 256)

__global__ void conv_rope(const float* __restrict__ x,  const float* __restrict__ wq,
                          const float* __restrict__ wk, const float* __restrict__ wv,
                          const float* __restrict__ wo,
                          float* __restrict__ rc, float* __restrict__ rs)
{
    int bid = blockIdx.x;
    if (bid >= CONV_BLKS) {   // rope table path
        int idx = (bid - CONV_BLKS) * 256 + threadIdx.x;
        if (idx >= S_LEN * 32) return;
        int s = idx >> 5, i = idx & 31;
        double ang = (double)s * pow(10000.0, -(double)i / 32.0);
        double sd, cd;
        sincos(ang, &sd, &cd);
        rc[idx] = (float)cd;
        rs[idx] = (float)sd;
        return;
    }
    int q = bid * 256 + threadIdx.x;
    if (q >= QTOT) return;
    const float* src;
    __half *dh, *dl;
    int lq;
    if (q < QX)                        { src = x;  dh = g_xh;  dl = nullptr; lq = q; }
    else if (q < QX + QWQ)             { src = wq; dh = g_wh;  dl = g_wl;   lq = q - QX; }
    else if (q < QX + QWQ + QWK)       { src = wk; dh = g_wh + DM * DM; dl = g_wl + DM * DM; lq = q - QX - QWQ; }
    else if (q < QX + QWQ + QWK + QWV) { src = wv; dh = g_wh + DM * DM + KV_DIM * DM; dl = g_wl + DM * DM + KV_DIM * DM; lq = q - QX - QWQ - QWK; }
    else                               { src = wo; dh = g_woh; dl = g_wol;  lq = q - QX - QWQ - QWK - QWV; }

    float4 v = ((const float4*)src)[lq];
    uint32_t h0, l0, h1, l1;
    split_h2(v.x, v.y, h0, l0);
    split_h2(v.z, v.w, h1, l1);
    ((uint32_t*)dh)[lq * 2] = h0; ((uint32_t*)dh)[lq * 2 + 1] = h1;
    if (dl) { ((uint32_t*)dl)[lq * 2] = l0; ((uint32_t*)dl)[lq * 2 + 1] = l1; }
}

// ---------------- fp16x2 GEMM: C[M,N] = A[M,K] @ B[N,K]^T ----------------
// A hi only; B hi+lo. BM=BN=128, BK=32, 256 thr (8 warps 4m x 2n), 2-stage cp.async.
#define GSTR 20                 // uints per smem row (16 data + 4 pad)
#define GTILE (128 * GSTR)      // 2560 uints = 10240 B

__global__ __launch_bounds__(256, 2) void gemm_h2(
    const __half* __restrict__ Ah,
    const __half* __restrict__ Bh, const __half* __restrict__ Bl,
    float* __restrict__ Cf, __half* __restrict__ Ch, __half* __restrict__ Cl,
    int M, int N, int K)
{
    extern __shared__ uint32_t gsm[];

    const int t    = threadIdx.x;
    const int lane = t & 31;
    const int warp = t >> 5;
    const int wm   = warp >> 1;
    const int wn   = warp & 1;
    const int m0   = blockIdx.y * 128;
    const int n0   = blockIdx.x * 128;

    const int lrow  = t >> 1;        // 0..127
    const int lhalf = t & 1;         // 16-half chunk select

    uint32_t smBase = (uint32_t)__cvta_generic_to_shared(gsm);
    const uint32_t aHiB = 0, bHiB = GTILE * 4, bLoB = 2u * GTILE * 4;
    const uint32_t bufStride = 3u * GTILE * 4;   // 30720 B per stage

    const uint32_t ldDst = (uint32_t)(lrow * GSTR + lhalf * 8) * 4;   // bytes

    const uint32_t aAddr = (uint32_t)((wm * 32 + (lane & 15)) * GSTR + (lane >> 4) * 4) * 4;
    const int bRow = wn * 64 + (lane & 7) + ((lane & 16) >> 1);
    const uint32_t bAddr = (uint32_t)(bRow * GSTR + ((lane & 8) ? 4 : 0)) * 4;

    const __half* aSrcH = Ah + (size_t)(m0 + lrow) * K + lhalf * 16;
    const __half* bSrcH = Bh + (size_t)(n0 + lrow) * K + lhalf * 16;
    const __half* bSrcL = Bl + (size_t)(n0 + lrow) * K + lhalf * 16;

    float acc[2][8][4];
#pragma unroll
    for (int i = 0; i < 2; ++i)
#pragma unroll
        for (int j = 0; j < 8; ++j)
#pragma unroll
            for (int k = 0; k < 4; ++k) acc[i][j][k] = 0.f;

    const int nt = K / 32;

    {   // prologue: stage 0
        uint32_t d = smBase + ldDst;
#pragma unroll
        for (int c = 0; c < 2; ++c) {
            cpa16(d + aHiB + c * 16, aSrcH + c * 8);
            cpa16(d + bHiB + c * 16, bSrcH + c * 8);
            cpa16(d + bLoB + c * 16, bSrcL + c * 8);
        }
        cp_commit();
    }

    for (int tt = 0; tt < nt; ++tt) {
        if (tt + 1 < nt) {
            const int k0 = (tt + 1) * 32;
            uint32_t d = smBase + (uint32_t)((tt + 1) & 1) * bufStride + ldDst;
#pragma unroll
            for (int c = 0; c < 2; ++c) {
                cpa16(d + aHiB + c * 16, aSrcH + k0 + c * 8);
                cpa16(d + bHiB + c * 16, bSrcH + k0 + c * 8);
                cpa16(d + bLoB + c * 16, bSrcL + k0 + c * 8);
            }
            cp_commit();
            cp_wait1();
        } else {
            cp_wait0();
        }
        __syncthreads();

        const uint32_t bb = smBase + (uint32_t)(tt & 1) * bufStride;

#pragma unroll
        for (int g = 0; g < 2; ++g) {       // two k16 groups
            const uint32_t gB = (uint32_t)(g * 8) * 4;
            uint32_t ah[2][4];
#pragma unroll
            for (int im = 0; im < 2; ++im)
                ldsm4(ah[im], bb + aHiB + aAddr + (uint32_t)(im * 16 * GSTR) * 4 + gB);

#pragma unroll
            for (int jj = 0; jj < 4; ++jj) {
                uint32_t bh[4], bl[4];
                const uint32_t ro = (uint32_t)(jj * 16 * GSTR) * 4;
                ldsm4(bh, bb + bHiB + bAddr + ro + gB);
                ldsm4(bl, bb + bLoB + bAddr + ro + gB);
#pragma unroll
                for (int hf = 0; hf < 2; ++hf) {
                    const int ntile = jj * 2 + hf;
#pragma unroll
                    for (int im = 0; im < 2; ++im) {
                        mma_f16(acc[im][ntile], ah[im], bl + hf * 2);
                        mma_f16(acc[im][ntile], ah[im], bh + hf * 2);
                    }
                }
            }
        }
        __syncthreads();
    }

    // epilogue
    const int r4 = lane >> 2;
    const int c4 = lane & 3;
    const int crow0 = m0 + wm * 32 + r4;
    const int ccol0 = n0 + wn * 64 + c4 * 2;
#pragma unroll
    for (int im = 0; im < 2; ++im) {
#pragma unroll
        for (int jn = 0; jn < 8; ++jn) {
            const int row = crow0 + im * 16;
            const int col = ccol0 + jn * 8;
            float v0 = acc[im][jn][0], v1 = acc[im][jn][1];
            float v2 = acc[im][jn][2], v3 = acc[im][jn][3];
            if (Cf) {
                *(float2*)&Cf[(size_t)row * N + col]       = make_float2(v0, v1);
                *(float2*)&Cf[(size_t)(row + 8) * N + col] = make_float2(v2, v3);
            } else {
                uint32_t h, l;
                split_h2(v0, v1, h, l);
                *(uint32_t*)&Ch[(size_t)row * N + col] = h;
                *(uint32_t*)&Cl[(size_t)row * N + col] = l;
                split_h2(v2, v3, h, l);
                *(uint32_t*)&Ch[(size_t)(row + 8) * N + col] = h;
                *(uint32_t*)&Cl[(size_t)(row + 8) * N + col] = l;
            }
        }
    }
}

// ---------------- rope_qk + vt transpose, fused ----------------
#define RQ_BLKS (S_LEN * 1280 / 256)
#define VT_BLKS ((S_LEN / 32) * (KV_DIM / 32))

__global__ void ropeqk_vt(const float* __restrict__ rc, const float* __restrict__ rs)
{
    __shared__ float tile[32][33];
    int bid = blockIdx.x;
    int t = threadIdx.x;

    if (bid >= RQ_BLKS) {   // V transpose path
        int b = bid - RQ_BLKS;
        const int s0 = (b & 63) * 32;
        const int c0 = (b >> 6) * 32;
        const int tx = t & 31, ty = t >> 5;
#pragma unroll
        for (int k = 0; k < 4; ++k) {
            int s = s0 + ty + k * 8;
            size_t src = (size_t)s * QKV_N + 2560 + c0 + tx;
            tile[ty + k * 8][tx] = __half2float(g_qkvh[src]) + __half2float(g_qkvl[src]);
        }
        __syncthreads();
#pragma unroll
        for (int k = 0; k < 4; ++k) {
            int c = c0 + ty + k * 8;
            float v = tile[tx][ty + k * 8];
            __half hh = __float2half_rn(v);
            g_vth[(size_t)c * S_LEN + s0 + tx] = hh;
            g_vtl[(size_t)c * S_LEN + s0 + tx] = __float2half_rn(v - __half2float(hh));
        }
        return;
    }

    int idx = bid * 256 + t;
    const int per_row = 1280;
    int s = idx / per_row;
    int r = idx - s * per_row;

    if (r < 1024) {        // Q -> fp16 hi, scaled
        int head = r >> 5, i = r & 31;
        int col = head * 64 + i;
        float c  = rc[(s << 5) + i];
        float sn = rs[(s << 5) + i];
        size_t b1 = (size_t)s * QKV_N + col;
        float x1 = __half2float(g_qkvh[b1])      + __half2float(g_qkvl[b1]);
        float x2 = __half2float(g_qkvh[b1 + 32]) + __half2float(g_qkvl[b1 + 32]);
        size_t d1 = (size_t)s * DM + col;
        g_qh[d1]      = __float2half_rn((x1 * c - x2 * sn) * 0.125f);
        g_qh[d1 + 32] = __float2half_rn((x2 * c + x1 * sn) * 0.125f);
    } else {               // K -> fp16 hi+lo
        int rr = r - 1024;
        int kvh = rr >> 5, i = rr & 31;
        float c  = rc[(s << 5) + i];
        float sn = rs[(s << 5) + i];
        size_t b1 = (size_t)s * QKV_N + 2048 + kvh * 64 + i;
        float x1 = __half2float(g_qkvh[b1])      + __half2float(g_qkvl[b1]);
        float x2 = __half2float(g_qkvh[b1 + 32]) + __half2float(g_qkvl[b1 + 32]);
        float y1 = x1 * c - x2 * sn;
        float y2 = x2 * c + x1 * sn;
        size_t d1 = (size_t)s * KV_DIM + kvh * 64 + i;
        __half h1 = __float2half_rn(y1), h2 = __float2half_rn(y2);
        g_kh[d1]      = h1; g_kl[d1]      = __float2half_rn(y1 - __half2float(h1));
        g_kh[d1 + 32] = h2; g_kl[d1 + 32] = __float2half_rn(y2 - __half2float(h2));
    }
}

// ---------------- Flash attention (fp16x2, cp.async double-buffered KV) ----------------
#define FSTR 36

__global__ __launch_bounds__(256) void fa_tc()
{
    extern __shared__ uint32_t fsm[];

    const int t    = threadIdx.x;
    const int lane = t & 31;
    const int warp = t >> 5;
    const int r4   = lane >> 2;
    const int c4   = lane & 3;
    const int s0   = blockIdx.x * 128;
    const int h    = blockIdx.y;
    const int kvh  = h / (NHEADS / NKVH);
    const int qcol = h * HDIM;
    const int kcol = kvh * HDIM;

    uint32_t smBase = (uint32_t)__cvta_generic_to_shared(fsm);
    const uint32_t QhB = 0;
    const uint32_t kvBase = 128u * FSTR * 4;
    const uint32_t kvStride = 4u * 64u * FSTR * 4;
    const uint32_t KhB = 0, KlB = 64u * FSTR * 4, VhB = 2u * 64u * FSTR * 4, VlB = 3u * 64u * FSTR * 4;

    const uint32_t aAddr = (uint32_t)((warp * 16 + (lane & 15)) * FSTR + (lane >> 4) * 4) * 4;
    const int bRow = (lane & 7) + ((lane & 16) >> 1);
    const uint32_t bAddr = (uint32_t)(bRow * FSTR + ((lane & 8) ? 4 : 0)) * 4;

    {
        const int row = t >> 1;
        const int cb  = (t & 1) * 4;
        const __half* qh = g_qh + (size_t)(s0 + row) * DM + qcol;
        uint32_t d = smBase + QhB + (uint32_t)(row * FSTR) * 4;
#pragma unroll
        for (int c = 0; c < 4; ++c)
            cpa16(d + (cb + c) * 16, qh + (cb + c) * 8);
    }

    const int kvRow = t >> 2;
    const int kvCb  = (t & 3) * 2;
    const __half* kSrcH = g_kh + (size_t)kvRow * KV_DIM + kcol;
    const __half* kSrcL = g_kl + (size_t)kvRow * KV_DIM + kcol;
    const __half* vSrcH = g_vth + (size_t)(kcol + kvRow) * S_LEN;
    const __half* vSrcL = g_vtl + (size_t)(kcol + kvRow) * S_LEN;
    const uint32_t kvDstRow = (uint32_t)(kvRow * FSTR) * 4;

    {
        uint32_t sb = smBase + kvBase + kvDstRow;
#pragma unroll
        for (int c = 0; c < 2; ++c) {
            cpa16(sb + KhB + (kvCb + c) * 16, kSrcH + (kvCb + c) * 8);
            cpa16(sb + KlB + (kvCb + c) * 16, kSrcL + (kvCb + c) * 8);
            cpa16(sb + VhB + (kvCb + c) * 16, vSrcH + (kvCb + c) * 8);
            cpa16(sb + VlB + (kvCb + c) * 16, vSrcL + (kvCb + c) * 8);
        }
        cp_commit();
    }

    float o[8][4];
#pragma unroll
    for (int j = 0; j < 8; ++j)
#pragma unroll
        for (int k = 0; k < 4; ++k) o[j][k] = 0.f;
    float mrow[2] = {-INFINITY, -INFINITY};
    float lrow[2] = {0.f, 0.f};

    const int NIT = S_LEN / 64;
    for (int it = 0; it < NIT; ++it) {
        if (it + 1 < NIT) {
            const int k0 = (it + 1) * 64;
            uint32_t sb = smBase + kvBase + (uint32_t)((it + 1) & 1) * kvStride + kvDstRow;
#pragma unroll
            for (int c = 0; c < 2; ++c) {
                cpa16(sb + KhB + (kvCb + c) * 16, kSrcH + (size_t)k0 * KV_DIM + (kvCb + c) * 8);
                cpa16(sb + KlB + (kvCb + c) * 16, kSrcL + (size_t)k0 * KV_DIM + (kvCb + c) * 8);
                cpa16(sb + VhB + (kvCb + c) * 16, vSrcH + k0 + (kvCb + c) * 8);
                cpa16(sb + VlB + (kvCb + c) * 16, vSrcL + k0 + (kvCb + c) * 8);
            }
            cp_commit();
            cp_wait1();
        } else {
            cp_wait0();
        }
        __syncthreads();

        const uint32_t kb = smBase + kvBase + (uint32_t)(it & 1) * kvStride;

        float s[8][4];
#pragma unroll
        for (int j = 0; j < 8; ++j)
#pragma unroll
            for (int k = 0; k < 4; ++k) s[j][k] = 0.f;

#pragma unroll
        for (int g = 0; g < 4; ++g) {
            const uint32_t gB = (uint32_t)(g * 8) * 4;
            uint32_t ah[4];
            ldsm4(ah, smBase + QhB + aAddr + gB);
#pragma unroll
            for (int jj = 0; jj < 4; ++jj) {
                const uint32_t ro = (uint32_t)(jj * 16 * FSTR) * 4;
                uint32_t bh[4], bl[4];
                ldsm4(bh, kb + KhB + bAddr + ro + gB);
                ldsm4(bl, kb + KlB + bAddr + ro + gB);
#pragma unroll
                for (int hf = 0; hf < 2; ++hf) {
                    mma_f16(s[jj * 2 + hf], ah, bl + hf * 2);
                    mma_f16(s[jj * 2 + hf], ah, bh + hf * 2);
                }
            }
        }

        float mx0 = -INFINITY, mx1 = -INFINITY;
#pragma unroll
        for (int jn = 0; jn < 8; ++jn) {
            mx0 = fmaxf(mx0, fmaxf(s[jn][0], s[jn][1]));
            mx1 = fmaxf(mx1, fmaxf(s[jn][2], s[jn][3]));
        }
        mx0 = fmaxf(mx0, __shfl_xor_sync(0xffffffffu, mx0, 1));
        mx0 = fmaxf(mx0, __shfl_xor_sync(0xffffffffu, mx0, 2));
        mx1 = fmaxf(mx1, __shfl_xor_sync(0xffffffffu, mx1, 1));
        mx1 = fmaxf(mx1, __shfl_xor_sync(0xffffffffu, mx1, 2));

        const float mn0 = fmaxf(mrow[0], mx0);
        const float mn1 = fmaxf(mrow[1], mx1);
        const float a0 = __expf(mrow[0] - mn0);
        const float a1 = __expf(mrow[1] - mn1);
        float rs0 = 0.f, rs1 = 0.f;
#pragma unroll
        for (int jn = 0; jn < 8; ++jn) {
            s[jn][0] = __expf(s[jn][0] - mn0); rs0 += s[jn][0];
            s[jn][1] = __expf(s[jn][1] - mn0); rs0 += s[jn][1];
            s[jn][2] = __expf(s[jn][2] - mn1); rs1 += s[jn][2];
            s[jn][3] = __expf(s[jn][3] - mn1); rs1 += s[jn][3];
        }
        rs0 += __shfl_xor_sync(0xffffffffu, rs0, 1);
        rs0 += __shfl_xor_sync(0xffffffffu, rs0, 2);
        rs1 += __shfl_xor_sync(0xffffffffu, rs1, 1);
        rs1 += __shfl_xor_sync(0xffffffffu, rs1, 2);

        lrow[0] = lrow[0] * a0 + rs0;
        lrow[1] = lrow[1] * a1 + rs1;
        mrow[0] = mn0;
        mrow[1] = mn1;
#pragma unroll
        for (int jn = 0; jn < 8; ++jn) {
            o[jn][0] *= a0; o[jn][1] *= a0;
            o[jn][2] *= a1; o[jn][3] *= a1;
        }

#pragma unroll
        for (int g = 0; g < 4; ++g) {
            uint32_t ph[4];
            ph[0] = pack_h2(s[2 * g][0],     s[2 * g][1]);
            ph[1] = pack_h2(s[2 * g][2],     s[2 * g][3]);
            ph[2] = pack_h2(s[2 * g + 1][0], s[2 * g + 1][1]);
            ph[3] = pack_h2(s[2 * g + 1][2], s[2 * g + 1][3]);
            const uint32_t gB = (uint32_t)(g * 8) * 4;
#pragma unroll
            for (int jj = 0; jj < 4; ++jj) {
                const uint32_t ro = (uint32_t)(jj * 16 * FSTR) * 4;
                uint32_t vh[4], vl[4];
                ldsm4(vh, kb + VhB + bAddr + ro + gB);
                ldsm4(vl, kb + VlB + bAddr + ro + gB);
#pragma unroll
                for (int hf = 0; hf < 2; ++hf) {
                    mma_f16(o[jj * 2 + hf], ph, vl + hf * 2);
                    mma_f16(o[jj * 2 + hf], ph, vh + hf * 2);
                }
            }
        }
        __syncthreads();
    }

    const float inv0 = 1.0f / lrow[0];
    const float inv1 = 1.0f / lrow[1];
    const int row0 = s0 + warp * 16 + r4;
#pragma unroll
    for (int jn = 0; jn < 8; ++jn) {
        const int col = qcol + jn * 8 + c4 * 2;
        *(uint32_t*)&g_ah[(size_t)row0 * DM + col] =
            pack_h2(o[jn][0] * inv0, o[jn][1] * inv0);
        *(uint32_t*)&g_ah[(size_t)(row0 + 8) * DM + col] =
            pack_h2(o[jn][2] * inv1, o[jn][3] * inv1);
    }
}

// ---------------- launch ----------------
extern "C" void kernel_launch(void* const* d_in, const int* in_sizes, int n_in,
                              void* d_out, int out_size)
{
    const float *x, *Wq, *Wk, *Wv, *Wo;
    if (in_sizes[0] == S_LEN * DM) {        // dict order [x, Wq, Wk, Wv, Wo]
        x  = (const float*)d_in[0];
        Wq = (const float*)d_in[1];
        Wk = (const float*)d_in[2];
        Wv = (const float*)d_in[3];
        Wo = (const float*)d_in[4];
    } else {                                 // sorted order [Wk, Wo, Wq, Wv, x]
        Wk = (const float*)d_in[0];
        Wo = (const float*)d_in[1];
        Wq = (const float*)d_in[2];
        Wv = (const float*)d_in[3];
        x  = (const float*)d_in[4];
    }
    float* out = (float*)d_out;

    float *rc, *rs;
    cudaGetSymbolAddress((void**)&rc, g_rc);
    cudaGetSymbolAddress((void**)&rs, g_rs);
    __half *xh, *wh, *wl, *woh, *wol, *qkvh, *qkvl, *ah;
    cudaGetSymbolAddress((void**)&xh, g_xh);
    cudaGetSymbolAddress((void**)&wh, g_wh);   cudaGetSymbolAddress((void**)&wl, g_wl);
    cudaGetSymbolAddress((void**)&woh, g_woh); cudaGetSymbolAddress((void**)&wol, g_wol);
    cudaGetSymbolAddress((void**)&qkvh, g_qkvh); cudaGetSymbolAddress((void**)&qkvl, g_qkvl);
    cudaGetSymbolAddress((void**)&ah, g_ah);

    const int gemm_smem = 2 * 3 * GTILE * sizeof(uint32_t);              // 61440
    const int fa_smem   = (128 + 2 * 4 * 64) * FSTR * sizeof(uint32_t);  // 92160
    cudaFuncSetAttribute(gemm_h2, cudaFuncAttributeMaxDynamicSharedMemorySize, gemm_smem);
    cudaFuncSetAttribute(fa_tc, cudaFuncAttributeMaxDynamicSharedMemorySize, fa_smem);

    // 1: conv + rope table (fused)
    conv_rope<<<CONV_BLKS + 256, 256>>>(x, Wq, Wk, Wv, Wo, rc, rs);

    // 2: fused QKV projection
    gemm_h2<<<dim3(QKV_N / 128, S_LEN / 128), 256, gemm_smem>>>(
        xh, wh, wl, nullptr, qkvh, qkvl, S_LEN, QKV_N, DM);

    // 3: rope_qk + V transpose (fused)
    ropeqk_vt<<<RQ_BLKS + VT_BLKS, 256>>>(rc, rs);

    // 4: flash attention  (empirical profile slot)
    fa_tc<<<dim3(S_LEN / 128, NHEADS), 256, fa_smem>>>();

    // 5: output projection
    gemm_h2<<<dim3(DM / 128, S_LEN / 128), 256, gemm_smem>>>(
        ah, woh, wol, out, nullptr, nullptr, S_LEN, DM, DM);
}

// round 11
// speedup vs baseline: 5.1978x; 1.1002x over previous
#include <cuda_runtime.h>
#include <cuda_fp16.h>
#include <math.h>
#include <stdint.h>

#define S_LEN   2048
#define DM      2048
#define KV_DIM  512
#define NHEADS  32
#define NKVH    8
#define HDIM    64
#define QKV_N   3072

// ---------------- fp16 hi/lo planes ----------------
__device__ __half g_xh[S_LEN * DM];                              // x hi only (A operand)
__device__ __half g_wh[QKV_N * DM],  g_wl[QKV_N * DM];           // Wq|Wk|Wv hi+lo
__device__ __half g_woh[DM * DM],    g_wol[DM * DM];             // Wo hi+lo
__device__ __half g_qkvh[S_LEN * QKV_N], g_qkvl[S_LEN * QKV_N];  // proj out hi+lo
__device__ __half g_qh[S_LEN * DM];                              // roped, scaled by 0.125*log2e
__device__ __half g_kh[S_LEN * KV_DIM], g_kl[S_LEN * KV_DIM];    // roped K hi+lo
__device__ __half g_vth[KV_DIM * S_LEN];                         // V^T hi only
__device__ __half g_ah[S_LEN * DM];                              // attn out hi
__device__ float g_rc[S_LEN * 32], g_rs[S_LEN * 32];

// ---------------- helpers ----------------
__device__ __forceinline__ uint32_t pack_h2(float e0, float e1) {
    __half2 h = __floats2half2_rn(e0, e1);
    return *(uint32_t*)&h;
}
__device__ __forceinline__ void split_h2(float x0, float x1, uint32_t& h, uint32_t& l) {
    float h0 = __half2float(__float2half_rn(x0));
    float h1 = __half2float(__float2half_rn(x1));
    h = pack_h2(h0, h1);
    l = pack_h2(x0 - h0, x1 - h1);
}
__device__ __forceinline__ void mma_f16(float* c, const uint32_t* a, const uint32_t* b) {
    asm volatile(
        "mma.sync.aligned.m16n8k16.row.col.f32.f16.f16.f32 "
        "{%0,%1,%2,%3}, {%4,%5,%6,%7}, {%8,%9}, {%0,%1,%2,%3};"
        : "+f"(c[0]), "+f"(c[1]), "+f"(c[2]), "+f"(c[3])
        : "r"(a[0]), "r"(a[1]), "r"(a[2]), "r"(a[3]), "r"(b[0]), "r"(b[1]));
}
__device__ __forceinline__ void ldsm4(uint32_t* r, uint32_t addr) {
    asm volatile("ldmatrix.sync.aligned.m8n8.x4.shared.b16 {%0,%1,%2,%3}, [%4];"
        : "=r"(r[0]), "=r"(r[1]), "=r"(r[2]), "=r"(r[3]) : "r"(addr));
}
__device__ __forceinline__ void cpa16(uint32_t dst, const void* src) {
    asm volatile("cp.async.cg.shared.global [%0], [%1], 16;" :: "r"(dst), "l"(src));
}
__device__ __forceinline__ void cp_commit() { asm volatile("cp.async.commit_group;"); }
__device__ __forceinline__ void cp_wait0()  { asm volatile("cp.async.wait_group 0;"); }
__device__ __forceinline__ void cp_wait1()  { asm volatile("cp.async.wait_group 1;"); }

// ---------------- conv (f32 -> fp16 planes) + rope table, fused ----------------
#define QX   (S_LEN * DM / 4)
#define QWQ  (DM * DM / 4)
#define QWK  (KV_DIM * DM / 4)
#define QWV  (KV_DIM * DM / 4)
#define QWO  (DM * DM / 4)
#define QTOT (QX + QWQ + QWK + QWV + QWO)
#define CONV_BLKS ((QTOT + 255) / 256)

__global__ void conv_rope(const float* __restrict__ x,  const float* __restrict__ wq,
                          const float* __restrict__ wk, const float* __restrict__ wv,
                          const float* __restrict__ wo,
                          float* __restrict__ rc, float* __restrict__ rs)
{
    int bid = blockIdx.x;
    if (bid >= CONV_BLKS) {   // rope table path
        int idx = (bid - CONV_BLKS) * 256 + threadIdx.x;
        if (idx >= S_LEN * 32) return;
        int s = idx >> 5, i = idx & 31;
        double ang = (double)s * pow(10000.0, -(double)i / 32.0);
        double sd, cd;
        sincos(ang, &sd, &cd);
        rc[idx] = (float)cd;
        rs[idx] = (float)sd;
        return;
    }
    int q = bid * 256 + threadIdx.x;
    if (q >= QTOT) return;
    const float* src;
    __half *dh, *dl;
    int lq;
    if (q < QX)                        { src = x;  dh = g_xh;  dl = nullptr; lq = q; }
    else if (q < QX + QWQ)             { src = wq; dh = g_wh;  dl = g_wl;   lq = q - QX; }
    else if (q < QX + QWQ + QWK)       { src = wk; dh = g_wh + DM * DM; dl = g_wl + DM * DM; lq = q - QX - QWQ; }
    else if (q < QX + QWQ + QWK + QWV) { src = wv; dh = g_wh + DM * DM + KV_DIM * DM; dl = g_wl + DM * DM + KV_DIM * DM; lq = q - QX - QWQ - QWK; }
    else                               { src = wo; dh = g_woh; dl = g_wol;  lq = q - QX - QWQ - QWK - QWV; }

    float4 v = ((const float4*)src)[lq];
    uint32_t h0, l0, h1, l1;
    split_h2(v.x, v.y, h0, l0);
    split_h2(v.z, v.w, h1, l1);
    ((uint32_t*)dh)[lq * 2] = h0; ((uint32_t*)dh)[lq * 2 + 1] = h1;
    if (dl) { ((uint32_t*)dl)[lq * 2] = l0; ((uint32_t*)dl)[lq * 2 + 1] = l1; }
}

// ---------------- fp16x2 GEMM (unchanged from R10) ----------------
#define GSTR 20
#define GTILE (128 * GSTR)

__global__ __launch_bounds__(256, 2) void gemm_h2(
    const __half* __restrict__ Ah,
    const __half* __restrict__ Bh, const __half* __restrict__ Bl,
    float* __restrict__ Cf, __half* __restrict__ Ch, __half* __restrict__ Cl,
    int M, int N, int K)
{
    extern __shared__ uint32_t gsm[];

    const int t    = threadIdx.x;
    const int lane = t & 31;
    const int warp = t >> 5;
    const int wm   = warp >> 1;
    const int wn   = warp & 1;
    const int m0   = blockIdx.y * 128;
    const int n0   = blockIdx.x * 128;

    const int lrow  = t >> 1;
    const int lhalf = t & 1;

    uint32_t smBase = (uint32_t)__cvta_generic_to_shared(gsm);
    const uint32_t aHiB = 0, bHiB = GTILE * 4, bLoB = 2u * GTILE * 4;
    const uint32_t bufStride = 3u * GTILE * 4;

    const uint32_t ldDst = (uint32_t)(lrow * GSTR + lhalf * 8) * 4;

    const uint32_t aAddr = (uint32_t)((wm * 32 + (lane & 15)) * GSTR + (lane >> 4) * 4) * 4;
    const int bRow = wn * 64 + (lane & 7) + ((lane & 16) >> 1);
    const uint32_t bAddr = (uint32_t)(bRow * GSTR + ((lane & 8) ? 4 : 0)) * 4;

    const __half* aSrcH = Ah + (size_t)(m0 + lrow) * K + lhalf * 16;
    const __half* bSrcH = Bh + (size_t)(n0 + lrow) * K + lhalf * 16;
    const __half* bSrcL = Bl + (size_t)(n0 + lrow) * K + lhalf * 16;

    float acc[2][8][4];
#pragma unroll
    for (int i = 0; i < 2; ++i)
#pragma unroll
        for (int j = 0; j < 8; ++j)
#pragma unroll
            for (int k = 0; k < 4; ++k) acc[i][j][k] = 0.f;

    const int nt = K / 32;

    {
        uint32_t d = smBase + ldDst;
#pragma unroll
        for (int c = 0; c < 2; ++c) {
            cpa16(d + aHiB + c * 16, aSrcH + c * 8);
            cpa16(d + bHiB + c * 16, bSrcH + c * 8);
            cpa16(d + bLoB + c * 16, bSrcL + c * 8);
        }
        cp_commit();
    }

    for (int tt = 0; tt < nt; ++tt) {
        if (tt + 1 < nt) {
            const int k0 = (tt + 1) * 32;
            uint32_t d = smBase + (uint32_t)((tt + 1) & 1) * bufStride + ldDst;
#pragma unroll
            for (int c = 0; c < 2; ++c) {
                cpa16(d + aHiB + c * 16, aSrcH + k0 + c * 8);
                cpa16(d + bHiB + c * 16, bSrcH + k0 + c * 8);
                cpa16(d + bLoB + c * 16, bSrcL + k0 + c * 8);
            }
            cp_commit();
            cp_wait1();
        } else {
            cp_wait0();
        }
        __syncthreads();

        const uint32_t bb = smBase + (uint32_t)(tt & 1) * bufStride;

#pragma unroll
        for (int g = 0; g < 2; ++g) {
            const uint32_t gB = (uint32_t)(g * 8) * 4;
            uint32_t ah[2][4];
#pragma unroll
            for (int im = 0; im < 2; ++im)
                ldsm4(ah[im], bb + aHiB + aAddr + (uint32_t)(im * 16 * GSTR) * 4 + gB);

#pragma unroll
            for (int jj = 0; jj < 4; ++jj) {
                uint32_t bh[4], bl[4];
                const uint32_t ro = (uint32_t)(jj * 16 * GSTR) * 4;
                ldsm4(bh, bb + bHiB + bAddr + ro + gB);
                ldsm4(bl, bb + bLoB + bAddr + ro + gB);
#pragma unroll
                for (int hf = 0; hf < 2; ++hf) {
                    const int ntile = jj * 2 + hf;
#pragma unroll
                    for (int im = 0; im < 2; ++im) {
                        mma_f16(acc[im][ntile], ah[im], bl + hf * 2);
                        mma_f16(acc[im][ntile], ah[im], bh + hf * 2);
                    }
                }
            }
        }
        __syncthreads();
    }

    const int r4 = lane >> 2;
    const int c4 = lane & 3;
    const int crow0 = m0 + wm * 32 + r4;
    const int ccol0 = n0 + wn * 64 + c4 * 2;
#pragma unroll
    for (int im = 0; im < 2; ++im) {
#pragma unroll
        for (int jn = 0; jn < 8; ++jn) {
            const int row = crow0 + im * 16;
            const int col = ccol0 + jn * 8;
            float v0 = acc[im][jn][0], v1 = acc[im][jn][1];
            float v2 = acc[im][jn][2], v3 = acc[im][jn][3];
            if (Cf) {
                *(float2*)&Cf[(size_t)row * N + col]       = make_float2(v0, v1);
                *(float2*)&Cf[(size_t)(row + 8) * N + col] = make_float2(v2, v3);
            } else {
                uint32_t h, l;
                split_h2(v0, v1, h, l);
                *(uint32_t*)&Ch[(size_t)row * N + col] = h;
                *(uint32_t*)&Cl[(size_t)row * N + col] = l;
                split_h2(v2, v3, h, l);
                *(uint32_t*)&Ch[(size_t)(row + 8) * N + col] = h;
                *(uint32_t*)&Cl[(size_t)(row + 8) * N + col] = l;
            }
        }
    }
}

// ---------------- rope_qk + vt transpose, fused ----------------
#define RQ_BLKS (S_LEN * 1280 / 256)
#define VT_BLKS ((S_LEN / 32) * (KV_DIM / 32))
#define QSCALE 0.180336880111124f   /* 0.125 * log2(e) */

__global__ void ropeqk_vt(const float* __restrict__ rc, const float* __restrict__ rs)
{
    __shared__ float tile[32][33];
    int bid = blockIdx.x;
    int t = threadIdx.x;

    if (bid >= RQ_BLKS) {   // V transpose path (hi only)
        int b = bid - RQ_BLKS;
        const int s0 = (b & 63) * 32;
        const int c0 = (b >> 6) * 32;
        const int tx = t & 31, ty = t >> 5;
#pragma unroll
        for (int k = 0; k < 4; ++k) {
            int s = s0 + ty + k * 8;
            size_t src = (size_t)s * QKV_N + 2560 + c0 + tx;
            tile[ty + k * 8][tx] = __half2float(g_qkvh[src]) + __half2float(g_qkvl[src]);
        }
        __syncthreads();
#pragma unroll
        for (int k = 0; k < 4; ++k) {
            int c = c0 + ty + k * 8;
            g_vth[(size_t)c * S_LEN + s0 + tx] = __float2half_rn(tile[tx][ty + k * 8]);
        }
        return;
    }

    int idx = bid * 256 + t;
    const int per_row = 1280;
    int s = idx / per_row;
    int r = idx - s * per_row;

    if (r < 1024) {        // Q -> fp16 hi, scaled into exp2 domain
        int head = r >> 5, i = r & 31;
        int col = head * 64 + i;
        float c  = rc[(s << 5) + i];
        float sn = rs[(s << 5) + i];
        size_t b1 = (size_t)s * QKV_N + col;
        float x1 = __half2float(g_qkvh[b1])      + __half2float(g_qkvl[b1]);
        float x2 = __half2float(g_qkvh[b1 + 32]) + __half2float(g_qkvl[b1 + 32]);
        size_t d1 = (size_t)s * DM + col;
        g_qh[d1]      = __float2half_rn((x1 * c - x2 * sn) * QSCALE);
        g_qh[d1 + 32] = __float2half_rn((x2 * c + x1 * sn) * QSCALE);
    } else {               // K -> fp16 hi+lo
        int rr = r - 1024;
        int kvh = rr >> 5, i = rr & 31;
        float c  = rc[(s << 5) + i];
        float sn = rs[(s << 5) + i];
        size_t b1 = (size_t)s * QKV_N + 2048 + kvh * 64 + i;
        float x1 = __half2float(g_qkvh[b1])      + __half2float(g_qkvl[b1]);
        float x2 = __half2float(g_qkvh[b1 + 32]) + __half2float(g_qkvl[b1 + 32]);
        float y1 = x1 * c - x2 * sn;
        float y2 = x2 * c + x1 * sn;
        size_t d1 = (size_t)s * KV_DIM + kvh * 64 + i;
        __half h1 = __float2half_rn(y1), h2 = __float2half_rn(y2);
        g_kh[d1]      = h1; g_kl[d1]      = __float2half_rn(y1 - __half2float(h1));
        g_kh[d1 + 32] = h2; g_kl[d1 + 32] = __float2half_rn(y2 - __half2float(h2));
    }
}

// ---------------- Flash attention: Q-frag hoist, V hi-only, exp2 softmax ----------------
#define FSTR 36

__global__ __launch_bounds__(256) void fa_tc()
{
    extern __shared__ uint32_t fsm[];

    const int t    = threadIdx.x;
    const int lane = t & 31;
    const int warp = t >> 5;
    const int r4   = lane >> 2;
    const int c4   = lane & 3;
    const int s0   = blockIdx.x * 128;
    const int h    = blockIdx.y;
    const int kvh  = h / (NHEADS / NKVH);
    const int qcol = h * HDIM;
    const int kcol = kvh * HDIM;

    uint32_t smBase = (uint32_t)__cvta_generic_to_shared(fsm);
    const uint32_t QhB = 0;
    const uint32_t kvBase = 128u * FSTR * 4;
    const uint32_t kvStride = 3u * 64u * FSTR * 4;      // Kh|Kl|Vh per stage
    const uint32_t KhB = 0, KlB = 64u * FSTR * 4, VhB = 2u * 64u * FSTR * 4;

    const uint32_t aAddr = (uint32_t)((warp * 16 + (lane & 15)) * FSTR + (lane >> 4) * 4) * 4;
    const int bRow = (lane & 7) + ((lane & 16) >> 1);
    const uint32_t bAddr = (uint32_t)(bRow * FSTR + ((lane & 8) ? 4 : 0)) * 4;

    // group 0: Q tile
    {
        const int row = t >> 1;
        const int cb  = (t & 1) * 4;
        const __half* qh = g_qh + (size_t)(s0 + row) * DM + qcol;
        uint32_t d = smBase + QhB + (uint32_t)(row * FSTR) * 4;
#pragma unroll
        for (int c = 0; c < 4; ++c)
            cpa16(d + (cb + c) * 16, qh + (cb + c) * 8);
        cp_commit();
    }

    const int kvRow = t >> 2;
    const int kvCb  = (t & 3) * 2;
    const __half* kSrcH = g_kh + (size_t)kvRow * KV_DIM + kcol;
    const __half* kSrcL = g_kl + (size_t)kvRow * KV_DIM + kcol;
    const __half* vSrcH = g_vth + (size_t)(kcol + kvRow) * S_LEN;
    const uint32_t kvDstRow = (uint32_t)(kvRow * FSTR) * 4;

    // group 1: KV stage 0
    {
        uint32_t sb = smBase + kvBase + kvDstRow;
#pragma unroll
        for (int c = 0; c < 2; ++c) {
            cpa16(sb + KhB + (kvCb + c) * 16, kSrcH + (kvCb + c) * 8);
            cpa16(sb + KlB + (kvCb + c) * 16, kSrcL + (kvCb + c) * 8);
            cpa16(sb + VhB + (kvCb + c) * 16, vSrcH + (kvCb + c) * 8);
        }
        cp_commit();
    }

    // wait Q (group 0) done, hoist Q fragments to registers
    uint32_t qfr[4][4];
    cp_wait1();
    __syncthreads();
#pragma unroll
    for (int g = 0; g < 4; ++g)
        ldsm4(qfr[g], smBase + QhB + aAddr + (uint32_t)(g * 8) * 4);

    float o[8][4];
#pragma unroll
    for (int j = 0; j < 8; ++j)
#pragma unroll
        for (int k = 0; k < 4; ++k) o[j][k] = 0.f;
    float mrow[2] = {-INFINITY, -INFINITY};
    float lrow[2] = {0.f, 0.f};

    const int NIT = S_LEN / 64;
    for (int it = 0; it < NIT; ++it) {
        if (it + 1 < NIT) {
            const int k0 = (it + 1) * 64;
            uint32_t sb = smBase + kvBase + (uint32_t)((it + 1) & 1) * kvStride + kvDstRow;
#pragma unroll
            for (int c = 0; c < 2; ++c) {
                cpa16(sb + KhB + (kvCb + c) * 16, kSrcH + (size_t)k0 * KV_DIM + (kvCb + c) * 8);
                cpa16(sb + KlB + (kvCb + c) * 16, kSrcL + (size_t)k0 * KV_DIM + (kvCb + c) * 8);
                cpa16(sb + VhB + (kvCb + c) * 16, vSrcH + k0 + (kvCb + c) * 8);
            }
            cp_commit();
            cp_wait1();
        } else {
            cp_wait0();
        }
        __syncthreads();

        const uint32_t kb = smBase + kvBase + (uint32_t)(it & 1) * kvStride;

        // ---- S = Q K^T (log2 domain) ----
        float s[8][4];
#pragma unroll
        for (int j = 0; j < 8; ++j)
#pragma unroll
            for (int k = 0; k < 4; ++k) s[j][k] = 0.f;

#pragma unroll
        for (int g = 0; g < 4; ++g) {
            const uint32_t gB = (uint32_t)(g * 8) * 4;
#pragma unroll
            for (int jj = 0; jj < 4; ++jj) {
                const uint32_t ro = (uint32_t)(jj * 16 * FSTR) * 4;
                uint32_t bh[4], bl[4];
                ldsm4(bh, kb + KhB + bAddr + ro + gB);
                ldsm4(bl, kb + KlB + bAddr + ro + gB);
#pragma unroll
                for (int hf = 0; hf < 2; ++hf) {
                    mma_f16(s[jj * 2 + hf], qfr[g], bl + hf * 2);
                    mma_f16(s[jj * 2 + hf], qfr[g], bh + hf * 2);
                }
            }
        }

        // ---- online softmax (exp2 domain) ----
        float mx0 = -INFINITY, mx1 = -INFINITY;
#pragma unroll
        for (int jn = 0; jn < 8; ++jn) {
            mx0 = fmaxf(mx0, fmaxf(s[jn][0], s[jn][1]));
            mx1 = fmaxf(mx1, fmaxf(s[jn][2], s[jn][3]));
        }
        mx0 = fmaxf(mx0, __shfl_xor_sync(0xffffffffu, mx0, 1));
        mx0 = fmaxf(mx0, __shfl_xor_sync(0xffffffffu, mx0, 2));
        mx1 = fmaxf(mx1, __shfl_xor_sync(0xffffffffu, mx1, 1));
        mx1 = fmaxf(mx1, __shfl_xor_sync(0xffffffffu, mx1, 2));

        const float mn0 = fmaxf(mrow[0], mx0);
        const float mn1 = fmaxf(mrow[1], mx1);
        const float a0 = exp2f(mrow[0] - mn0);
        const float a1 = exp2f(mrow[1] - mn1);
        float rs0 = 0.f, rs1 = 0.f;
#pragma unroll
        for (int jn = 0; jn < 8; ++jn) {
            s[jn][0] = exp2f(s[jn][0] - mn0); rs0 += s[jn][0];
            s[jn][1] = exp2f(s[jn][1] - mn0); rs0 += s[jn][1];
            s[jn][2] = exp2f(s[jn][2] - mn1); rs1 += s[jn][2];
            s[jn][3] = exp2f(s[jn][3] - mn1); rs1 += s[jn][3];
        }
        rs0 += __shfl_xor_sync(0xffffffffu, rs0, 1);
        rs0 += __shfl_xor_sync(0xffffffffu, rs0, 2);
        rs1 += __shfl_xor_sync(0xffffffffu, rs1, 1);
        rs1 += __shfl_xor_sync(0xffffffffu, rs1, 2);

        lrow[0] = lrow[0] * a0 + rs0;
        lrow[1] = lrow[1] * a1 + rs1;
        mrow[0] = mn0;
        mrow[1] = mn1;
#pragma unroll
        for (int jn = 0; jn < 8; ++jn) {
            o[jn][0] *= a0; o[jn][1] *= a0;
            o[jn][2] *= a1; o[jn][3] *= a1;
        }

        // ---- O += P V (V hi only) ----
#pragma unroll
        for (int g = 0; g < 4; ++g) {
            uint32_t ph[4];
            ph[0] = pack_h2(s[2 * g][0],     s[2 * g][1]);
            ph[1] = pack_h2(s[2 * g][2],     s[2 * g][3]);
            ph[2] = pack_h2(s[2 * g + 1][0], s[2 * g + 1][1]);
            ph[3] = pack_h2(s[2 * g + 1][2], s[2 * g + 1][3]);
            const uint32_t gB = (uint32_t)(g * 8) * 4;
#pragma unroll
            for (int jj = 0; jj < 4; ++jj) {
                const uint32_t ro = (uint32_t)(jj * 16 * FSTR) * 4;
                uint32_t vh[4];
                ldsm4(vh, kb + VhB + bAddr + ro + gB);
#pragma unroll
                for (int hf = 0; hf < 2; ++hf)
                    mma_f16(o[jj * 2 + hf], ph, vh + hf * 2);
            }
        }
        __syncthreads();
    }

    const float inv0 = 1.0f / lrow[0];
    const float inv1 = 1.0f / lrow[1];
    const int row0 = s0 + warp * 16 + r4;
#pragma unroll
    for (int jn = 0; jn < 8; ++jn) {
        const int col = qcol + jn * 8 + c4 * 2;
        *(uint32_t*)&g_ah[(size_t)row0 * DM + col] =
            pack_h2(o[jn][0] * inv0, o[jn][1] * inv0);
        *(uint32_t*)&g_ah[(size_t)(row0 + 8) * DM + col] =
            pack_h2(o[jn][2] * inv1, o[jn][3] * inv1);
    }
}

// ---------------- launch ----------------
extern "C" void kernel_launch(void* const* d_in, const int* in_sizes, int n_in,
                              void* d_out, int out_size)
{
    const float *x, *Wq, *Wk, *Wv, *Wo;
    if (in_sizes[0] == S_LEN * DM) {        // dict order [x, Wq, Wk, Wv, Wo]
        x  = (const float*)d_in[0];
        Wq = (const float*)d_in[1];
        Wk = (const float*)d_in[2];
        Wv = (const float*)d_in[3];
        Wo = (const float*)d_in[4];
    } else {                                 // sorted order [Wk, Wo, Wq, Wv, x]
        Wk = (const float*)d_in[0];
        Wo = (const float*)d_in[1];
        Wq = (const float*)d_in[2];
        Wv = (const float*)d_in[3];
        x  = (const float*)d_in[4];
    }
    float* out = (float*)d_out;

    float *rc, *rs;
    cudaGetSymbolAddress((void**)&rc, g_rc);
    cudaGetSymbolAddress((void**)&rs, g_rs);
    __half *xh, *wh, *wl, *woh, *wol, *qkvh, *qkvl, *ah;
    cudaGetSymbolAddress((void**)&xh, g_xh);
    cudaGetSymbolAddress((void**)&wh, g_wh);   cudaGetSymbolAddress((void**)&wl, g_wl);
    cudaGetSymbolAddress((void**)&woh, g_woh); cudaGetSymbolAddress((void**)&wol, g_wol);
    cudaGetSymbolAddress((void**)&qkvh, g_qkvh); cudaGetSymbolAddress((void**)&qkvl, g_qkvl);
    cudaGetSymbolAddress((void**)&ah, g_ah);

    const int gemm_smem = 2 * 3 * GTILE * sizeof(uint32_t);              // 61440
    const int fa_smem   = (128 + 2 * 3 * 64) * FSTR * sizeof(uint32_t);  // 73728
    cudaFuncSetAttribute(gemm_h2, cudaFuncAttributeMaxDynamicSharedMemorySize, gemm_smem);
    cudaFuncSetAttribute(fa_tc, cudaFuncAttributeMaxDynamicSharedMemorySize, fa_smem);

    // 1: conv + rope table (fused)
    conv_rope<<<CONV_BLKS + 256, 256>>>(x, Wq, Wk, Wv, Wo, rc, rs);

    // 2: fused QKV projection
    gemm_h2<<<dim3(QKV_N / 128, S_LEN / 128), 256, gemm_smem>>>(
        xh, wh, wl, nullptr, qkvh, qkvl, S_LEN, QKV_N, DM);

    // 3: rope_qk + V transpose (fused)
    ropeqk_vt<<<RQ_BLKS + VT_BLKS, 256>>>(rc, rs);

    // 4: flash attention  (profile slot)
    fa_tc<<<dim3(S_LEN / 128, NHEADS), 256, fa_smem>>>();

    // 5: output projection
    gemm_h2<<<dim3(DM / 128, S_LEN / 128), 256, gemm_smem>>>(
        ah, woh, wol, out, nullptr, nullptr, S_LEN, DM, DM);
}